// round 9
// baseline (speedup 1.0000x reference)
#include <cuda_runtime.h>
#include <math.h>

#define NB 8
#define NH 8
#define NS 6144
#define NSM1 6143
#define NDM 512
#define NDK 64
#define NWN 6113
#define NM 32
#define NWC 12

__device__ float g_WkM[512 * 512];
__device__ float g_WqM[512 * 512];
__device__ float g_WvM[512 * 512];
__device__ float g_WOMt[512 * 512];
__device__ float g_Khat[(size_t)NB * NH * NS * NDK];
__device__ float g_Qhat[NB * NH * NM * NDK];
__device__ float g_qa[NB * NH * 32];
__device__ float g_qp[NB * NH * 16];
__device__ float g_tn[(size_t)NB * NH * NS];
__device__ float g_d2[(size_t)NB * NH * NS];
__device__ float g_d3[(size_t)NB * NH * NS];
__device__ float g_attn[(size_t)NB * NH * NS];
__device__ float g_alast[NB * NH];
__device__ float g_ctxp[NB * NWC * NH * NDM];
__device__ float g_hist[NB * NH * NDK];
__device__ float g_GI[31 * NB * 192];
__device__ float g_res[NB * NDK];

// ---- masked weights ----
__global__ void prep_kernel(const float* __restrict__ Wk, const float* __restrict__ Wq,
                            const float* __restrict__ Wv, const float* __restrict__ WO,
                            const int* __restrict__ G) {
    int i = blockIdx.x * blockDim.x + threadIdx.x;
    if (i >= 512 * 512) return;
    int row = i >> 9, d = i & 511;
    float gm = (float)G[(row & 63) * 64 + (d & 63)];
    g_WkM[i] = Wk[i] * gm;
    g_WqM[i] = Wq[i] * gm;
    g_WvM[i] = Wv[i] * gm;
    float gm2 = (float)G[(d & 63) * 64 + (row & 63)];
    g_WOMt[i] = WO[d * 512 + row] * gm2;  // [e][d] = WO[d][e]*mask
}

// ---- K projection, all heads batched: grid(48,4,8), 256 thr, 128x128 tile ----
__global__ void __launch_bounds__(256) kproj_kernel(const float* __restrict__ mem,
                                                    const float* __restrict__ xpre,
                                                    const float* __restrict__ bk) {
    __shared__ __align__(16) float As[32 * 132];
    __shared__ __align__(16) float Bs[32 * 132];
    int s0 = blockIdx.x * 128, n0 = blockIdx.y * 128, b = blockIdx.z;
    int tid = threadIdx.x;
    int ty = tid >> 4, tx = tid & 15;
    float acc[8][8] = {};
    for (int d0 = 0; d0 < 512; d0 += 32) {
        __syncthreads();
#pragma unroll
        for (int it = 0; it < 4; it++) {
            int idx = it * 256 + tid;
            int rr = idx >> 3, kq = (idx & 7) * 4;
            int s = s0 + rr;
            const float* src = (s < NSM1) ? (mem + ((size_t)b * NSM1 + s) * 512 + d0 + kq)
                                          : (xpre + b * 512 + d0 + kq);
            float4 v = *(const float4*)src;
            As[(kq + 0) * 132 + rr] = v.x; As[(kq + 1) * 132 + rr] = v.y;
            As[(kq + 2) * 132 + rr] = v.z; As[(kq + 3) * 132 + rr] = v.w;
            float4 wv = *(const float4*)(g_WkM + (size_t)(n0 + rr) * 512 + d0 + kq);
            Bs[(kq + 0) * 132 + rr] = wv.x; Bs[(kq + 1) * 132 + rr] = wv.y;
            Bs[(kq + 2) * 132 + rr] = wv.z; Bs[(kq + 3) * 132 + rr] = wv.w;
        }
        __syncthreads();
#pragma unroll
        for (int kk = 0; kk < 32; kk++) {
            float4 a0 = *(const float4*)&As[kk * 132 + ty * 4];
            float4 a1 = *(const float4*)&As[kk * 132 + 64 + ty * 4];
            float4 b0 = *(const float4*)&Bs[kk * 132 + tx * 4];
            float4 b1 = *(const float4*)&Bs[kk * 132 + 64 + tx * 4];
            float ar[8] = {a0.x, a0.y, a0.z, a0.w, a1.x, a1.y, a1.z, a1.w};
            float br[8] = {b0.x, b0.y, b0.z, b0.w, b1.x, b1.y, b1.z, b1.w};
#pragma unroll
            for (int i = 0; i < 8; i++)
#pragma unroll
                for (int j = 0; j < 8; j++) acc[i][j] += ar[i] * br[j];
        }
    }
    float bias[8];
#pragma unroll
    for (int j = 0; j < 4; j++) {
        bias[j] = bk[n0 + tx * 4 + j];
        bias[4 + j] = bk[n0 + 64 + tx * 4 + j];
    }
    int h0 = n0 >> 6;
#pragma unroll
    for (int i = 0; i < 8; i++) {
        int r = (i < 4) ? (ty * 4 + i) : (64 + ty * 4 + (i - 4));
        int s = s0 + r;
        float v[8];
        float ss0 = 0.f, ss1 = 0.f;
#pragma unroll
        for (int j = 0; j < 8; j++) {
            v[j] = acc[i][j] + bias[j];
            if (j < 4) ss0 += v[j] * v[j]; else ss1 += v[j] * v[j];
        }
#pragma unroll
        for (int o = 8; o; o >>= 1) {
            ss0 += __shfl_xor_sync(0xffffffffu, ss0, o);
            ss1 += __shfl_xor_sync(0xffffffffu, ss1, o);
        }
        float i0 = 1.0f / fmaxf(sqrtf(ss0), 1e-12f);
        float i1 = 1.0f / fmaxf(sqrtf(ss1), 1e-12f);
        float* d0p = g_Khat + (((size_t)(b * 8 + h0)) * NS + s) * 64 + tx * 4;
        float* d1p = g_Khat + (((size_t)(b * 8 + h0 + 1)) * NS + s) * 64 + tx * 4;
        *(float4*)d0p = make_float4(v[0] * i0, v[1] * i0, v[2] * i0, v[3] * i0);
        *(float4*)d1p = make_float4(v[4] * i1, v[5] * i1, v[6] * i1, v[7] * i1);
    }
}

// ---- Q projection (last 32 rows) : grid(8h,8b), 256 thr ----
__global__ void __launch_bounds__(256) qproj_kernel(const float* __restrict__ mem,
                                                    const float* __restrict__ xpre,
                                                    const float* __restrict__ bq) {
    int h = blockIdx.x, b = blockIdx.y, tid = threadIdx.x;
    int m = tid >> 3, cg = (tid & 7) * 8;
    float acc[8] = {};
    int s = 6112 + m;
    const float* xr = (s < NSM1) ? (mem + ((size_t)b * NSM1 + s) * 512) : (xpre + b * 512);
    const float* wb = g_WqM + (h * 64 + cg) * 512;
    for (int d = 0; d < 512; d += 4) {
        float4 xv = *(const float4*)(xr + d);
#pragma unroll
        for (int c = 0; c < 8; c++) {
            float4 wv = *(const float4*)(wb + c * 512 + d);
            acc[c] += xv.x * wv.x + xv.y * wv.y + xv.z * wv.z + xv.w * wv.w;
        }
    }
    __shared__ float qs[32 * 65];
#pragma unroll
    for (int c = 0; c < 8; c++) qs[m * 65 + cg + c] = acc[c] + bq[h * 64 + cg + c];
    __syncthreads();
    if (tid < 32) {
        float ss = 0.f;
        for (int c = 0; c < 64; c++) { float v = qs[tid * 65 + c]; ss += v * v; }
        float inv = 1.f / fmaxf(sqrtf(ss), 1e-12f);
        float* dst = g_Qhat + ((b * 8 + h) * 32 + tid) * 64;
        for (int c = 0; c < 64; c++) dst[c] = qs[tid * 65 + c] * inv;
    }
}

// ---- tn: banded correlation : grid(48,8,8), 128 thr, float4 LDS, stride 36 ----
__global__ void __launch_bounds__(128) tn_kernel() {
    int j0 = blockIdx.x * 128, h = blockIdx.y, b = blockIdx.z;
    int bh = b * 8 + h, tid = threadIdx.x;
    __shared__ __align__(16) float qs[32 * 64];
    __shared__ __align__(16) float Ks[159 * 36];
    for (int u = tid; u < 512; u += 128)
        ((float4*)qs)[u] = ((const float4*)(g_Qhat + bh * 2048))[u];
    float acc = 0.f;
    const float* kb = g_Khat + (size_t)bh * NS * 64;
    for (int p = 0; p < 2; p++) {
        __syncthreads();
        for (int v = tid; v < 159 * 8; v += 128) {
            int u = v >> 3, c4 = (v & 7) * 4;
            int s = j0 + u;
            float4 val = make_float4(0.f, 0.f, 0.f, 0.f);
            if (s < NS) val = *(const float4*)(kb + (size_t)s * 64 + p * 32 + c4);
            *(float4*)&Ks[u * 36 + c4] = val;
        }
        __syncthreads();
#pragma unroll 4
        for (int m = 0; m < 32; m++) {
            const float* qrow = qs + m * 64 + p * 32;
            const float* krow = Ks + (tid + m) * 36;
#pragma unroll
            for (int c = 0; c < 8; c++) {
                float4 kv = *(const float4*)(krow + c * 4);
                float4 qv = *(const float4*)(qrow + c * 4);
                acc += qv.x * kv.x + qv.y * kv.y + qv.z * kv.z + qv.w * kv.w;
            }
        }
    }
    int j = j0 + tid;
    if (j < NWN) g_tn[(size_t)bh * NS + j] = acc * (1.0f / 32.0f);
}

// ---- qa_last, qp_last ----
__global__ void qa_kernel(const float* __restrict__ aux, const float* __restrict__ Wqa,
                          const float* __restrict__ bqa) {
    int b = blockIdx.x, tid = threadIdx.x;
    int h = tid >> 5, c = tid & 31;
    const float* row = aux + ((size_t)b * NS + NS - 1) * 256;
    const float* wr = Wqa + (h * 32 + c) * 256;
    float acc = bqa[h * 32 + c];
    for (int a = 0; a < 256; a += 4) {
        float4 xv = *(const float4*)(row + a);
        float4 wv = *(const float4*)(wr + a);
        acc += xv.x * wv.x + xv.y * wv.y + xv.z * wv.z + xv.w * wv.w;
    }
    float ss = acc * acc;
#pragma unroll
    for (int o = 16; o; o >>= 1) ss += __shfl_xor_sync(0xffffffffu, ss, o);
    g_qa[(b * 8 + h) * 32 + c] = acc / fmaxf(sqrtf(ss), 1e-12f);
}

__global__ void qp_kernel(const float* __restrict__ pos, const float* __restrict__ Wqp,
                          const float* __restrict__ bqp) {
    int b = blockIdx.x, tid = threadIdx.x;
    int h = tid >> 4, c = tid & 15;
    const float* row = pos + ((size_t)b * NS + NS - 1) * 128;
    const float* wr = Wqp + (h * 16 + c) * 128;
    float acc = bqp[h * 16 + c];
    for (int a = 0; a < 128; a += 4) {
        float4 xv = *(const float4*)(row + a);
        float4 wv = *(const float4*)(wr + a);
        acc += xv.x * wv.x + xv.y * wv.y + xv.z * wv.z + xv.w * wv.w;
    }
    float ss = acc * acc;
#pragma unroll
    for (int o = 8; o; o >>= 1) ss += __shfl_xor_sync(0xffffffffu, ss, o);
    g_qp[(b * 8 + h) * 16 + c] = acc / fmaxf(sqrtf(ss), 1e-12f);
}

// ---- dot2 batched: grid(48,2,8), 256 thr, 128x128 tile, K=256 ----
__global__ void __launch_bounds__(256) dot2_kernel(const float* __restrict__ aux,
                                                   const float* __restrict__ Wka,
                                                   const float* __restrict__ bka) {
    __shared__ __align__(16) float As[32 * 132];
    __shared__ __align__(16) float Bs[32 * 132];
    int j0 = blockIdx.x * 128, n0 = blockIdx.y * 128, b = blockIdx.z;
    int tid = threadIdx.x;
    int ty = tid >> 4, tx = tid & 15;
    float acc[8][8] = {};
    for (int d0 = 0; d0 < 256; d0 += 32) {
        __syncthreads();
#pragma unroll
        for (int it = 0; it < 4; it++) {
            int idx = it * 256 + tid;
            int rr = idx >> 3, kq = (idx & 7) * 4;
            int j = j0 + rr;
            float4 v = make_float4(0.f, 0.f, 0.f, 0.f);
            if (j < NWN) v = *(const float4*)(aux + ((size_t)b * NS + 31 + j) * 256 + d0 + kq);
            As[(kq + 0) * 132 + rr] = v.x; As[(kq + 1) * 132 + rr] = v.y;
            As[(kq + 2) * 132 + rr] = v.z; As[(kq + 3) * 132 + rr] = v.w;
            float4 wv = *(const float4*)(Wka + (size_t)(n0 + rr) * 256 + d0 + kq);
            Bs[(kq + 0) * 132 + rr] = wv.x; Bs[(kq + 1) * 132 + rr] = wv.y;
            Bs[(kq + 2) * 132 + rr] = wv.z; Bs[(kq + 3) * 132 + rr] = wv.w;
        }
        __syncthreads();
#pragma unroll
        for (int kk = 0; kk < 32; kk++) {
            float4 a0 = *(const float4*)&As[kk * 132 + ty * 4];
            float4 a1 = *(const float4*)&As[kk * 132 + 64 + ty * 4];
            float4 b0 = *(const float4*)&Bs[kk * 132 + tx * 4];
            float4 b1 = *(const float4*)&Bs[kk * 132 + 64 + tx * 4];
            float ar[8] = {a0.x, a0.y, a0.z, a0.w, a1.x, a1.y, a1.z, a1.w};
            float br[8] = {b0.x, b0.y, b0.z, b0.w, b1.x, b1.y, b1.z, b1.w};
#pragma unroll
            for (int i = 0; i < 8; i++)
#pragma unroll
                for (int j = 0; j < 8; j++) acc[i][j] += ar[i] * br[j];
        }
    }
    int hA = (n0 >> 5) + (tx >> 3);
    int hB = hA + 2;
    const float* qaA = g_qa + (b * 8 + hA) * 32;
    const float* qaB = g_qa + (b * 8 + hB) * 32;
    float biasA[4], biasB[4];
#pragma unroll
    for (int j = 0; j < 4; j++) {
        biasA[j] = bka[n0 + tx * 4 + j];
        biasB[j] = bka[n0 + 64 + tx * 4 + j];
    }
    int c32 = (tx & 7) * 4;
#pragma unroll
    for (int i = 0; i < 8; i++) {
        int r = (i < 4) ? (ty * 4 + i) : (64 + ty * 4 + (i - 4));
        int jrow = j0 + r;
        float ss0 = 0.f, dt0 = 0.f, ss1 = 0.f, dt1 = 0.f;
#pragma unroll
        for (int j = 0; j < 4; j++) {
            float v0 = acc[i][j] + biasA[j];
            float v1 = acc[i][4 + j] + biasB[j];
            ss0 += v0 * v0; dt0 += qaA[c32 + j] * v0;
            ss1 += v1 * v1; dt1 += qaB[c32 + j] * v1;
        }
#pragma unroll
        for (int o = 1; o < 8; o <<= 1) {
            ss0 += __shfl_xor_sync(0xffffffffu, ss0, o);
            dt0 += __shfl_xor_sync(0xffffffffu, dt0, o);
            ss1 += __shfl_xor_sync(0xffffffffu, ss1, o);
            dt1 += __shfl_xor_sync(0xffffffffu, dt1, o);
        }
        if ((tx & 7) == 0 && jrow < NWN) {
            g_d2[(size_t)(b * 8 + hA) * NS + jrow] = dt0 / fmaxf(sqrtf(ss0), 1e-12f);
            g_d2[(size_t)(b * 8 + hB) * NS + jrow] = dt1 / fmaxf(sqrtf(ss1), 1e-12f);
        }
    }
}

// ---- dot3 batched: grid(48,1,8), 256 thr, 128x128, K=128 ----
__global__ void __launch_bounds__(256) dot3_kernel(const float* __restrict__ pos,
                                                   const float* __restrict__ Wkp,
                                                   const float* __restrict__ bkp) {
    __shared__ __align__(16) float As[32 * 132];
    __shared__ __align__(16) float Bs[32 * 132];
    int j0 = blockIdx.x * 128, b = blockIdx.z;
    int tid = threadIdx.x;
    int ty = tid >> 4, tx = tid & 15;
    float acc[8][8] = {};
    for (int d0 = 0; d0 < 128; d0 += 32) {
        __syncthreads();
#pragma unroll
        for (int it = 0; it < 4; it++) {
            int idx = it * 256 + tid;
            int rr = idx >> 3, kq = (idx & 7) * 4;
            int j = j0 + rr;
            float4 v = make_float4(0.f, 0.f, 0.f, 0.f);
            if (j < NWN) v = *(const float4*)(pos + ((size_t)b * NS + 31 + j) * 128 + d0 + kq);
            As[(kq + 0) * 132 + rr] = v.x; As[(kq + 1) * 132 + rr] = v.y;
            As[(kq + 2) * 132 + rr] = v.z; As[(kq + 3) * 132 + rr] = v.w;
            float4 wv = *(const float4*)(Wkp + (size_t)rr * 128 + d0 + kq);
            Bs[(kq + 0) * 132 + rr] = wv.x; Bs[(kq + 1) * 132 + rr] = wv.y;
            Bs[(kq + 2) * 132 + rr] = wv.z; Bs[(kq + 3) * 132 + rr] = wv.w;
        }
        __syncthreads();
#pragma unroll
        for (int kk = 0; kk < 32; kk++) {
            float4 a0 = *(const float4*)&As[kk * 132 + ty * 4];
            float4 a1 = *(const float4*)&As[kk * 132 + 64 + ty * 4];
            float4 b0 = *(const float4*)&Bs[kk * 132 + tx * 4];
            float4 b1 = *(const float4*)&Bs[kk * 132 + 64 + tx * 4];
            float ar[8] = {a0.x, a0.y, a0.z, a0.w, a1.x, a1.y, a1.z, a1.w};
            float br[8] = {b0.x, b0.y, b0.z, b0.w, b1.x, b1.y, b1.z, b1.w};
#pragma unroll
            for (int i = 0; i < 8; i++)
#pragma unroll
                for (int j = 0; j < 8; j++) acc[i][j] += ar[i] * br[j];
        }
    }
    int hA = tx >> 2;
    int hB = hA + 4;
    const float* qpA = g_qp + (b * 8 + hA) * 16;
    const float* qpB = g_qp + (b * 8 + hB) * 16;
    float biasA[4], biasB[4];
#pragma unroll
    for (int j = 0; j < 4; j++) {
        biasA[j] = bkp[tx * 4 + j];
        biasB[j] = bkp[64 + tx * 4 + j];
    }
    int c16 = (tx & 3) * 4;
#pragma unroll
    for (int i = 0; i < 8; i++) {
        int r = (i < 4) ? (ty * 4 + i) : (64 + ty * 4 + (i - 4));
        int jrow = j0 + r;
        float ss0 = 0.f, dt0 = 0.f, ss1 = 0.f, dt1 = 0.f;
#pragma unroll
        for (int j = 0; j < 4; j++) {
            float v0 = acc[i][j] + biasA[j];
            float v1 = acc[i][4 + j] + biasB[j];
            ss0 += v0 * v0; dt0 += qpA[c16 + j] * v0;
            ss1 += v1 * v1; dt1 += qpB[c16 + j] * v1;
        }
#pragma unroll
        for (int o = 1; o < 4; o <<= 1) {
            ss0 += __shfl_xor_sync(0xffffffffu, ss0, o);
            dt0 += __shfl_xor_sync(0xffffffffu, dt0, o);
            ss1 += __shfl_xor_sync(0xffffffffu, ss1, o);
            dt1 += __shfl_xor_sync(0xffffffffu, dt1, o);
        }
        if ((tx & 3) == 0 && jrow < NWN) {
            g_d3[(size_t)(b * 8 + hA) * NS + jrow] = dt0 / fmaxf(sqrtf(ss0), 1e-12f);
            g_d3[(size_t)(b * 8 + hB) * NS + jrow] = dt1 / fmaxf(sqrtf(ss1), 1e-12f);
        }
    }
}

// ---- softmax over Wn : grid(64), 256 thr ----
__global__ void __launch_bounds__(256) softmax_kernel(const float* __restrict__ w,
                                                      const float* __restrict__ wa,
                                                      const float* __restrict__ wp) {
    int bh = blockIdx.x, tid = threadIdx.x;
    float w0 = w[0], w1 = wa[0], w2 = wp[0];
    size_t base = (size_t)bh * NS;
    __shared__ float red[256];
    float mx = -1e30f;
    for (int j = tid; j < NWN; j += 256) {
        float z = w0 * g_tn[base + j] + w1 * g_d2[base + j] + w2 * g_d3[base + j];
        g_attn[base + j] = z;
        mx = fmaxf(mx, z);
    }
    red[tid] = mx; __syncthreads();
    for (int o = 128; o; o >>= 1) { if (tid < o) red[tid] = fmaxf(red[tid], red[tid + o]); __syncthreads(); }
    mx = red[0]; __syncthreads();
    float sum = 0.f;
    for (int j = tid; j < NWN; j += 256) {
        float e = __expf(g_attn[base + j] - mx);
        g_attn[base + j] = e;
        sum += e;
    }
    red[tid] = sum; __syncthreads();
    for (int o = 128; o; o >>= 1) { if (tid < o) red[tid] += red[tid + o]; __syncthreads(); }
    float inv = 1.f / red[0];
    __syncthreads();
    for (int j = tid; j < NWN; j += 256) g_attn[base + j] *= inv;
    __syncthreads();
    if (tid == 0) g_alast[bh] = g_attn[base + NWN - 1];
}

// ---- ctx partial: grid(12,8), 512 thr ----
__global__ void __launch_bounds__(512) ctxp_kernel(const float* __restrict__ mem) {
    int wc = blockIdx.x, b = blockIdx.y, tid = threadIdx.x;
    __shared__ float at[8 * 512];
    int w0 = wc * 512;
    for (int u = tid; u < 4096; u += 512) {
        int h = u >> 9, ww = u & 511;
        int w = w0 + ww;
        at[h * 512 + ww] = (w < NWN - 1) ? g_attn[(size_t)(b * 8 + h) * NS + w] : 0.f;
    }
    __syncthreads();
    float acc[8] = {};
    const float* mb = mem + ((size_t)b * NSM1 + 31 + w0) * 512 + tid;
    int wlim = (NWN - 1) - w0; if (wlim > 512) wlim = 512;
    for (int ww = 0; ww < wlim; ww++) {
        float x = mb[(size_t)ww * 512];
#pragma unroll
        for (int h2 = 0; h2 < 8; h2++) acc[h2] += at[h2 * 512 + ww] * x;
    }
#pragma unroll
    for (int h2 = 0; h2 < 8; h2++)
        g_ctxp[(((b * NWC + wc) * 8 + h2) << 9) + tid] = acc[h2];
}

// ---- hist : grid(8b,8h), 256 thr ----
__global__ void __launch_bounds__(256) hist_kernel(const float* __restrict__ bv) {
    int b = blockIdx.x, h = blockIdx.y, tid = threadIdx.x;
    __shared__ float ctxs[512];
    __shared__ float red[256];
    for (int d = tid; d < 512; d += 256) {
        float s = 0.f;
        for (int wc = 0; wc < NWC; wc++)
            s += g_ctxp[(((b * NWC + wc) * 8 + h) << 9) + d];
        ctxs[d] = s;
    }
    __syncthreads();
    int kk = tid >> 2, q = (tid & 3) * 128;
    const float* wr = g_WvM + (h * 64 + kk) * 512 + q;
    float acc = 0.f;
    for (int d = 0; d < 128; d += 4) {
        float4 wv = *(const float4*)(wr + d);
        acc += wv.x * ctxs[q + d] + wv.y * ctxs[q + d + 1] + wv.z * ctxs[q + d + 2] + wv.w * ctxs[q + d + 3];
    }
    red[tid] = acc;
    __syncthreads();
    if (tid < 64) {
        float a1 = 1.0f - g_alast[b * 8 + h];
        float s = red[tid * 4] + red[tid * 4 + 1] + red[tid * 4 + 2] + red[tid * 4 + 3];
        g_hist[(b * 8 + h) * 64 + tid] = s + bv[h * 64 + tid] * a1;
    }
}

// ---- GRU gi precompute : grid(31,8), 192 thr ----
__global__ void gi_kernel(const float* __restrict__ mem, const float* __restrict__ W_ih,
                          const float* __restrict__ b_ih) {
    int t = blockIdx.x, b = blockIdx.y, j = threadIdx.x;
    const float* xr = mem + ((size_t)b * NSM1 + 6112 + t) * 512;
    const float* wr = W_ih + j * 512;
    float acc = b_ih[j];
    for (int d = 0; d < 512; d += 4) {
        float4 xv = *(const float4*)(xr + d);
        float4 wv = *(const float4*)(wr + d);
        acc += xv.x * wv.x + xv.y * wv.y + xv.z * wv.z + xv.w * wv.w;
    }
    g_GI[(t * 8 + b) * 192 + j] = acc;
}

// ---- GRU scan : 1 block, 512 thr ----
__global__ void __launch_bounds__(512) scan_kernel(const float* __restrict__ W_hh,
                                                   const float* __restrict__ b_hh) {
    int tid = threadIdx.x;
    int b = tid >> 6, kk = tid & 63;
    __shared__ float hs[8 * 64];
    hs[tid] = 0.f;
    __syncthreads();
    float bhr = b_hh[kk], bhz = b_hh[64 + kk], bhn = b_hh[128 + kk];
    const float* wr = W_hh + kk * 64;
    const float* wz = W_hh + (64 + kk) * 64;
    const float* wn = W_hh + (128 + kk) * 64;
    for (int t = 0; t < 31; t++) {
        float hr = bhr, hz = bhz, hn = bhn;
        const float* hb = hs + b * 64;
#pragma unroll 8
        for (int e = 0; e < 64; e++) {
            float he = hb[e];
            hr += wr[e] * he; hz += wz[e] * he; hn += wn[e] * he;
        }
        const float* gi = g_GI + (t * 8 + b) * 192;
        float r = 1.f / (1.f + __expf(-(gi[kk] + hr)));
        float z = 1.f / (1.f + __expf(-(gi[64 + kk] + hz)));
        float nst = tanhf(gi[128 + kk] + r * hn);
        float hold = hb[kk];
        float hnew = (1.f - z) * nst + z * hold;
        __syncthreads();
        hs[tid] = hnew;
        __syncthreads();
    }
    g_res[tid] = hs[tid];
}

// ---- final output : grid(8), 512 thr ----
__global__ void __launch_bounds__(512) final_kernel(const float* __restrict__ xpre,
                                                    const float* __restrict__ bO,
                                                    float* __restrict__ out) {
    int b = blockIdx.x, tid = threadIdx.x;
    __shared__ float det[512];
    {
        int h = tid >> 6, kk = tid & 63;
        det[tid] = g_hist[(b * 8 + h) * 64 + kk] + g_alast[b * 8 + h] * g_res[b * 64 + kk];
    }
    __syncthreads();
    float acc = 0.f;
    for (int e = 0; e < 512; e++) acc += det[e] * g_WOMt[e * 512 + tid];
    out[b * 512 + tid] = xpre[b * 512 + tid] + acc + bO[tid];
}

extern "C" void kernel_launch(void* const* d_in, const int* in_sizes, int n_in,
                              void* d_out, int out_size) {
    const float* mem  = (const float*)d_in[0];
    const float* xpre = (const float*)d_in[1];
    const float* aux  = (const float*)d_in[2];
    const float* pos  = (const float*)d_in[3];
    const float* Wq   = (const float*)d_in[4];
    const float* bq   = (const float*)d_in[5];
    const float* Wk   = (const float*)d_in[6];
    const float* bk   = (const float*)d_in[7];
    const float* Wv   = (const float*)d_in[8];
    const float* bv   = (const float*)d_in[9];
    const float* Wqa  = (const float*)d_in[10];
    const float* bqa  = (const float*)d_in[11];
    const float* Wka  = (const float*)d_in[12];
    const float* bka  = (const float*)d_in[13];
    const float* Wqp  = (const float*)d_in[14];
    const float* bqp  = (const float*)d_in[15];
    const float* Wkp  = (const float*)d_in[16];
    const float* bkp  = (const float*)d_in[17];
    const float* W_ih = (const float*)d_in[18];
    const float* W_hh = (const float*)d_in[19];
    const float* b_ih = (const float*)d_in[20];
    const float* b_hh = (const float*)d_in[21];
    const float* WO   = (const float*)d_in[22];
    const float* bO   = (const float*)d_in[23];
    const float* w    = (const float*)d_in[24];
    const float* wa   = (const float*)d_in[25];
    const float* wp   = (const float*)d_in[26];
    const int*   G    = (const int*)d_in[27];
    float* out = (float*)d_out;

    // Order chosen so the ncu single-capture (4th kernel launch) lands on tn_kernel.
    prep_kernel<<<(512 * 512 + 255) / 256, 256>>>(Wk, Wq, Wv, WO, G);
    kproj_kernel<<<dim3(48, 4, 8), 256>>>(mem, xpre, bk);
    qproj_kernel<<<dim3(8, 8), 256>>>(mem, xpre, bq);
    tn_kernel<<<dim3(48, 8, 8), 128>>>();
    qa_kernel<<<8, 256>>>(aux, Wqa, bqa);
    qp_kernel<<<8, 128>>>(pos, Wqp, bqp);
    dot2_kernel<<<dim3(48, 2, 8), 256>>>(aux, Wka, bka);
    dot3_kernel<<<dim3(48, 1, 8), 256>>>(pos, Wkp, bkp);
    softmax_kernel<<<64, 256>>>(w, wa, wp);
    ctxp_kernel<<<dim3(NWC, 8), 512>>>(mem);
    hist_kernel<<<dim3(8, 8), 256>>>(bv);
    gi_kernel<<<dim3(31, 8), 192>>>(mem, W_ih, b_ih);
    scan_kernel<<<1, 512>>>(W_hh, b_hh);
    final_kernel<<<8, 512>>>(xpre, bO, out);
}

// round 10
// speedup vs baseline: 1.0095x; 1.0095x over previous
#include <cuda_runtime.h>
#include <math.h>

#define NB 8
#define NH 8
#define NS 6144
#define NSM1 6143
#define NDM 512
#define NDK 64
#define NWN 6113
#define NM 32
#define NWC 24
#define WWIN 256

__device__ float g_WkM[512 * 512];
__device__ float g_WqM[512 * 512];
__device__ float g_WvM[512 * 512];
__device__ float g_WOMt[512 * 512];
__device__ float g_Khat[(size_t)NB * NH * NS * NDK];
__device__ float g_Qhat[NB * NH * NM * NDK];
__device__ float g_qa[NB * NH * 32];
__device__ float g_qp[NB * NH * 16];
__device__ float g_tn[(size_t)NB * NH * NS];
__device__ float g_d2[(size_t)NB * NH * NS];
__device__ float g_d3[(size_t)NB * NH * NS];
__device__ float g_attn[(size_t)NB * NH * NS];
__device__ float g_alast[NB * NH];
__device__ float g_ctxp[NB * NWC * NH * NDM];
__device__ float g_hist[NB * NH * NDK];
__device__ float g_GI[31 * NB * 192];
__device__ float g_res[NB * NDK];

// ---- masked weights ----
__global__ void prep_kernel(const float* __restrict__ Wk, const float* __restrict__ Wq,
                            const float* __restrict__ Wv, const float* __restrict__ WO,
                            const int* __restrict__ G) {
    int i = blockIdx.x * blockDim.x + threadIdx.x;
    if (i >= 512 * 512) return;
    int row = i >> 9, d = i & 511;
    float gm = (float)G[(row & 63) * 64 + (d & 63)];
    g_WkM[i] = Wk[i] * gm;
    g_WqM[i] = Wq[i] * gm;
    g_WvM[i] = Wv[i] * gm;
    float gm2 = (float)G[(d & 63) * 64 + (row & 63)];
    g_WOMt[i] = WO[d * 512 + row] * gm2;  // [e][d] = WO[d][e]*mask
}

// ---- K projection, all heads batched: grid(48,4,8), 256 thr, 128x128 tile ----
__global__ void __launch_bounds__(256) kproj_kernel(const float* __restrict__ mem,
                                                    const float* __restrict__ xpre,
                                                    const float* __restrict__ bk) {
    __shared__ __align__(16) float As[32 * 132];
    __shared__ __align__(16) float Bs[32 * 132];
    int s0 = blockIdx.x * 128, n0 = blockIdx.y * 128, b = blockIdx.z;
    int tid = threadIdx.x;
    int ty = tid >> 4, tx = tid & 15;
    float acc[8][8] = {};
    for (int d0 = 0; d0 < 512; d0 += 32) {
        __syncthreads();
#pragma unroll
        for (int it = 0; it < 4; it++) {
            int idx = it * 256 + tid;
            int rr = idx >> 3, kq = (idx & 7) * 4;
            int s = s0 + rr;
            const float* src = (s < NSM1) ? (mem + ((size_t)b * NSM1 + s) * 512 + d0 + kq)
                                          : (xpre + b * 512 + d0 + kq);
            float4 v = *(const float4*)src;
            As[(kq + 0) * 132 + rr] = v.x; As[(kq + 1) * 132 + rr] = v.y;
            As[(kq + 2) * 132 + rr] = v.z; As[(kq + 3) * 132 + rr] = v.w;
            float4 wv = *(const float4*)(g_WkM + (size_t)(n0 + rr) * 512 + d0 + kq);
            Bs[(kq + 0) * 132 + rr] = wv.x; Bs[(kq + 1) * 132 + rr] = wv.y;
            Bs[(kq + 2) * 132 + rr] = wv.z; Bs[(kq + 3) * 132 + rr] = wv.w;
        }
        __syncthreads();
#pragma unroll
        for (int kk = 0; kk < 32; kk++) {
            float4 a0 = *(const float4*)&As[kk * 132 + ty * 4];
            float4 a1 = *(const float4*)&As[kk * 132 + 64 + ty * 4];
            float4 b0 = *(const float4*)&Bs[kk * 132 + tx * 4];
            float4 b1 = *(const float4*)&Bs[kk * 132 + 64 + tx * 4];
            float ar[8] = {a0.x, a0.y, a0.z, a0.w, a1.x, a1.y, a1.z, a1.w};
            float br[8] = {b0.x, b0.y, b0.z, b0.w, b1.x, b1.y, b1.z, b1.w};
#pragma unroll
            for (int i = 0; i < 8; i++)
#pragma unroll
                for (int j = 0; j < 8; j++) acc[i][j] += ar[i] * br[j];
        }
    }
    float bias[8];
#pragma unroll
    for (int j = 0; j < 4; j++) {
        bias[j] = bk[n0 + tx * 4 + j];
        bias[4 + j] = bk[n0 + 64 + tx * 4 + j];
    }
    int h0 = n0 >> 6;
#pragma unroll
    for (int i = 0; i < 8; i++) {
        int r = (i < 4) ? (ty * 4 + i) : (64 + ty * 4 + (i - 4));
        int s = s0 + r;
        float v[8];
        float ss0 = 0.f, ss1 = 0.f;
#pragma unroll
        for (int j = 0; j < 8; j++) {
            v[j] = acc[i][j] + bias[j];
            if (j < 4) ss0 += v[j] * v[j]; else ss1 += v[j] * v[j];
        }
#pragma unroll
        for (int o = 8; o; o >>= 1) {
            ss0 += __shfl_xor_sync(0xffffffffu, ss0, o);
            ss1 += __shfl_xor_sync(0xffffffffu, ss1, o);
        }
        float i0 = 1.0f / fmaxf(sqrtf(ss0), 1e-12f);
        float i1 = 1.0f / fmaxf(sqrtf(ss1), 1e-12f);
        float* d0p = g_Khat + (((size_t)(b * 8 + h0)) * NS + s) * 64 + tx * 4;
        float* d1p = g_Khat + (((size_t)(b * 8 + h0 + 1)) * NS + s) * 64 + tx * 4;
        *(float4*)d0p = make_float4(v[0] * i0, v[1] * i0, v[2] * i0, v[3] * i0);
        *(float4*)d1p = make_float4(v[4] * i1, v[5] * i1, v[6] * i1, v[7] * i1);
    }
}

// ---- Q projection (last 32 rows) : grid(8h,8b), 256 thr ----
__global__ void __launch_bounds__(256) qproj_kernel(const float* __restrict__ mem,
                                                    const float* __restrict__ xpre,
                                                    const float* __restrict__ bq) {
    int h = blockIdx.x, b = blockIdx.y, tid = threadIdx.x;
    int m = tid >> 3, cg = (tid & 7) * 8;
    float acc[8] = {};
    int s = 6112 + m;
    const float* xr = (s < NSM1) ? (mem + ((size_t)b * NSM1 + s) * 512) : (xpre + b * 512);
    const float* wb = g_WqM + (h * 64 + cg) * 512;
    for (int d = 0; d < 512; d += 4) {
        float4 xv = *(const float4*)(xr + d);
#pragma unroll
        for (int c = 0; c < 8; c++) {
            float4 wv = *(const float4*)(wb + c * 512 + d);
            acc[c] += xv.x * wv.x + xv.y * wv.y + xv.z * wv.z + xv.w * wv.w;
        }
    }
    __shared__ float qs[32 * 65];
#pragma unroll
    for (int c = 0; c < 8; c++) qs[m * 65 + cg + c] = acc[c] + bq[h * 64 + cg + c];
    __syncthreads();
    if (tid < 32) {
        float ss = 0.f;
        for (int c = 0; c < 64; c++) { float v = qs[tid * 65 + c]; ss += v * v; }
        float inv = 1.f / fmaxf(sqrtf(ss), 1e-12f);
        float* dst = g_Qhat + ((b * 8 + h) * 32 + tid) * 64;
        for (int c = 0; c < 64; c++) dst[c] = qs[tid * 65 + c] * inv;
    }
}

// ---- tn: banded correlation : grid(48,8,8), 128 thr, float4 LDS, stride 36 ----
__global__ void __launch_bounds__(128) tn_kernel() {
    int j0 = blockIdx.x * 128, h = blockIdx.y, b = blockIdx.z;
    int bh = b * 8 + h, tid = threadIdx.x;
    __shared__ __align__(16) float qs[32 * 64];
    __shared__ __align__(16) float Ks[159 * 36];
    for (int u = tid; u < 512; u += 128)
        ((float4*)qs)[u] = ((const float4*)(g_Qhat + bh * 2048))[u];
    float acc = 0.f;
    const float* kb = g_Khat + (size_t)bh * NS * 64;
    for (int p = 0; p < 2; p++) {
        __syncthreads();
        for (int v = tid; v < 159 * 8; v += 128) {
            int u = v >> 3, c4 = (v & 7) * 4;
            int s = j0 + u;
            float4 val = make_float4(0.f, 0.f, 0.f, 0.f);
            if (s < NS) val = *(const float4*)(kb + (size_t)s * 64 + p * 32 + c4);
            *(float4*)&Ks[u * 36 + c4] = val;
        }
        __syncthreads();
#pragma unroll 4
        for (int m = 0; m < 32; m++) {
            const float* qrow = qs + m * 64 + p * 32;
            const float* krow = Ks + (tid + m) * 36;
#pragma unroll
            for (int c = 0; c < 8; c++) {
                float4 kv = *(const float4*)(krow + c * 4);
                float4 qv = *(const float4*)(qrow + c * 4);
                acc += qv.x * kv.x + qv.y * kv.y + qv.z * kv.z + qv.w * kv.w;
            }
        }
    }
    int j = j0 + tid;
    if (j < NWN) g_tn[(size_t)bh * NS + j] = acc * (1.0f / 32.0f);
}

// ---- qa_last, qp_last ----
__global__ void qa_kernel(const float* __restrict__ aux, const float* __restrict__ Wqa,
                          const float* __restrict__ bqa) {
    int b = blockIdx.x, tid = threadIdx.x;
    int h = tid >> 5, c = tid & 31;
    const float* row = aux + ((size_t)b * NS + NS - 1) * 256;
    const float* wr = Wqa + (h * 32 + c) * 256;
    float acc = bqa[h * 32 + c];
    for (int a = 0; a < 256; a += 4) {
        float4 xv = *(const float4*)(row + a);
        float4 wv = *(const float4*)(wr + a);
        acc += xv.x * wv.x + xv.y * wv.y + xv.z * wv.z + xv.w * wv.w;
    }
    float ss = acc * acc;
#pragma unroll
    for (int o = 16; o; o >>= 1) ss += __shfl_xor_sync(0xffffffffu, ss, o);
    g_qa[(b * 8 + h) * 32 + c] = acc / fmaxf(sqrtf(ss), 1e-12f);
}

__global__ void qp_kernel(const float* __restrict__ pos, const float* __restrict__ Wqp,
                          const float* __restrict__ bqp) {
    int b = blockIdx.x, tid = threadIdx.x;
    int h = tid >> 4, c = tid & 15;
    const float* row = pos + ((size_t)b * NS + NS - 1) * 128;
    const float* wr = Wqp + (h * 16 + c) * 128;
    float acc = bqp[h * 16 + c];
    for (int a = 0; a < 128; a += 4) {
        float4 xv = *(const float4*)(row + a);
        float4 wv = *(const float4*)(wr + a);
        acc += xv.x * wv.x + xv.y * wv.y + xv.z * wv.z + xv.w * wv.w;
    }
    float ss = acc * acc;
#pragma unroll
    for (int o = 8; o; o >>= 1) ss += __shfl_xor_sync(0xffffffffu, ss, o);
    g_qp[(b * 8 + h) * 16 + c] = acc / fmaxf(sqrtf(ss), 1e-12f);
}

// ---- dot2 batched: grid(48,2,8), 256 thr, 128x128 tile, K=256 ----
__global__ void __launch_bounds__(256) dot2_kernel(const float* __restrict__ aux,
                                                   const float* __restrict__ Wka,
                                                   const float* __restrict__ bka) {
    __shared__ __align__(16) float As[32 * 132];
    __shared__ __align__(16) float Bs[32 * 132];
    int j0 = blockIdx.x * 128, n0 = blockIdx.y * 128, b = blockIdx.z;
    int tid = threadIdx.x;
    int ty = tid >> 4, tx = tid & 15;
    float acc[8][8] = {};
    for (int d0 = 0; d0 < 256; d0 += 32) {
        __syncthreads();
#pragma unroll
        for (int it = 0; it < 4; it++) {
            int idx = it * 256 + tid;
            int rr = idx >> 3, kq = (idx & 7) * 4;
            int j = j0 + rr;
            float4 v = make_float4(0.f, 0.f, 0.f, 0.f);
            if (j < NWN) v = *(const float4*)(aux + ((size_t)b * NS + 31 + j) * 256 + d0 + kq);
            As[(kq + 0) * 132 + rr] = v.x; As[(kq + 1) * 132 + rr] = v.y;
            As[(kq + 2) * 132 + rr] = v.z; As[(kq + 3) * 132 + rr] = v.w;
            float4 wv = *(const float4*)(Wka + (size_t)(n0 + rr) * 256 + d0 + kq);
            Bs[(kq + 0) * 132 + rr] = wv.x; Bs[(kq + 1) * 132 + rr] = wv.y;
            Bs[(kq + 2) * 132 + rr] = wv.z; Bs[(kq + 3) * 132 + rr] = wv.w;
        }
        __syncthreads();
#pragma unroll
        for (int kk = 0; kk < 32; kk++) {
            float4 a0 = *(const float4*)&As[kk * 132 + ty * 4];
            float4 a1 = *(const float4*)&As[kk * 132 + 64 + ty * 4];
            float4 b0 = *(const float4*)&Bs[kk * 132 + tx * 4];
            float4 b1 = *(const float4*)&Bs[kk * 132 + 64 + tx * 4];
            float ar[8] = {a0.x, a0.y, a0.z, a0.w, a1.x, a1.y, a1.z, a1.w};
            float br[8] = {b0.x, b0.y, b0.z, b0.w, b1.x, b1.y, b1.z, b1.w};
#pragma unroll
            for (int i = 0; i < 8; i++)
#pragma unroll
                for (int j = 0; j < 8; j++) acc[i][j] += ar[i] * br[j];
        }
    }
    int hA = (n0 >> 5) + (tx >> 3);
    int hB = hA + 2;
    const float* qaA = g_qa + (b * 8 + hA) * 32;
    const float* qaB = g_qa + (b * 8 + hB) * 32;
    float biasA[4], biasB[4];
#pragma unroll
    for (int j = 0; j < 4; j++) {
        biasA[j] = bka[n0 + tx * 4 + j];
        biasB[j] = bka[n0 + 64 + tx * 4 + j];
    }
    int c32 = (tx & 7) * 4;
#pragma unroll
    for (int i = 0; i < 8; i++) {
        int r = (i < 4) ? (ty * 4 + i) : (64 + ty * 4 + (i - 4));
        int jrow = j0 + r;
        float ss0 = 0.f, dt0 = 0.f, ss1 = 0.f, dt1 = 0.f;
#pragma unroll
        for (int j = 0; j < 4; j++) {
            float v0 = acc[i][j] + biasA[j];
            float v1 = acc[i][4 + j] + biasB[j];
            ss0 += v0 * v0; dt0 += qaA[c32 + j] * v0;
            ss1 += v1 * v1; dt1 += qaB[c32 + j] * v1;
        }
#pragma unroll
        for (int o = 1; o < 8; o <<= 1) {
            ss0 += __shfl_xor_sync(0xffffffffu, ss0, o);
            dt0 += __shfl_xor_sync(0xffffffffu, dt0, o);
            ss1 += __shfl_xor_sync(0xffffffffu, ss1, o);
            dt1 += __shfl_xor_sync(0xffffffffu, dt1, o);
        }
        if ((tx & 7) == 0 && jrow < NWN) {
            g_d2[(size_t)(b * 8 + hA) * NS + jrow] = dt0 / fmaxf(sqrtf(ss0), 1e-12f);
            g_d2[(size_t)(b * 8 + hB) * NS + jrow] = dt1 / fmaxf(sqrtf(ss1), 1e-12f);
        }
    }
}

// ---- dot3 batched: grid(48,1,8), 256 thr, 128x128, K=128 ----
__global__ void __launch_bounds__(256) dot3_kernel(const float* __restrict__ pos,
                                                   const float* __restrict__ Wkp,
                                                   const float* __restrict__ bkp) {
    __shared__ __align__(16) float As[32 * 132];
    __shared__ __align__(16) float Bs[32 * 132];
    int j0 = blockIdx.x * 128, b = blockIdx.z;
    int tid = threadIdx.x;
    int ty = tid >> 4, tx = tid & 15;
    float acc[8][8] = {};
    for (int d0 = 0; d0 < 128; d0 += 32) {
        __syncthreads();
#pragma unroll
        for (int it = 0; it < 4; it++) {
            int idx = it * 256 + tid;
            int rr = idx >> 3, kq = (idx & 7) * 4;
            int j = j0 + rr;
            float4 v = make_float4(0.f, 0.f, 0.f, 0.f);
            if (j < NWN) v = *(const float4*)(pos + ((size_t)b * NS + 31 + j) * 128 + d0 + kq);
            As[(kq + 0) * 132 + rr] = v.x; As[(kq + 1) * 132 + rr] = v.y;
            As[(kq + 2) * 132 + rr] = v.z; As[(kq + 3) * 132 + rr] = v.w;
            float4 wv = *(const float4*)(Wkp + (size_t)rr * 128 + d0 + kq);
            Bs[(kq + 0) * 132 + rr] = wv.x; Bs[(kq + 1) * 132 + rr] = wv.y;
            Bs[(kq + 2) * 132 + rr] = wv.z; Bs[(kq + 3) * 132 + rr] = wv.w;
        }
        __syncthreads();
#pragma unroll
        for (int kk = 0; kk < 32; kk++) {
            float4 a0 = *(const float4*)&As[kk * 132 + ty * 4];
            float4 a1 = *(const float4*)&As[kk * 132 + 64 + ty * 4];
            float4 b0 = *(const float4*)&Bs[kk * 132 + tx * 4];
            float4 b1 = *(const float4*)&Bs[kk * 132 + 64 + tx * 4];
            float ar[8] = {a0.x, a0.y, a0.z, a0.w, a1.x, a1.y, a1.z, a1.w};
            float br[8] = {b0.x, b0.y, b0.z, b0.w, b1.x, b1.y, b1.z, b1.w};
#pragma unroll
            for (int i = 0; i < 8; i++)
#pragma unroll
                for (int j = 0; j < 8; j++) acc[i][j] += ar[i] * br[j];
        }
    }
    int hA = tx >> 2;
    int hB = hA + 4;
    const float* qpA = g_qp + (b * 8 + hA) * 16;
    const float* qpB = g_qp + (b * 8 + hB) * 16;
    float biasA[4], biasB[4];
#pragma unroll
    for (int j = 0; j < 4; j++) {
        biasA[j] = bkp[tx * 4 + j];
        biasB[j] = bkp[64 + tx * 4 + j];
    }
    int c16 = (tx & 3) * 4;
#pragma unroll
    for (int i = 0; i < 8; i++) {
        int r = (i < 4) ? (ty * 4 + i) : (64 + ty * 4 + (i - 4));
        int jrow = j0 + r;
        float ss0 = 0.f, dt0 = 0.f, ss1 = 0.f, dt1 = 0.f;
#pragma unroll
        for (int j = 0; j < 4; j++) {
            float v0 = acc[i][j] + biasA[j];
            float v1 = acc[i][4 + j] + biasB[j];
            ss0 += v0 * v0; dt0 += qpA[c16 + j] * v0;
            ss1 += v1 * v1; dt1 += qpB[c16 + j] * v1;
        }
#pragma unroll
        for (int o = 1; o < 4; o <<= 1) {
            ss0 += __shfl_xor_sync(0xffffffffu, ss0, o);
            dt0 += __shfl_xor_sync(0xffffffffu, dt0, o);
            ss1 += __shfl_xor_sync(0xffffffffu, ss1, o);
            dt1 += __shfl_xor_sync(0xffffffffu, dt1, o);
        }
        if ((tx & 3) == 0 && jrow < NWN) {
            g_d3[(size_t)(b * 8 + hA) * NS + jrow] = dt0 / fmaxf(sqrtf(ss0), 1e-12f);
            g_d3[(size_t)(b * 8 + hB) * NS + jrow] = dt1 / fmaxf(sqrtf(ss1), 1e-12f);
        }
    }
}

// ---- softmax over Wn : grid(64), 256 thr ----
__global__ void __launch_bounds__(256) softmax_kernel(const float* __restrict__ w,
                                                      const float* __restrict__ wa,
                                                      const float* __restrict__ wp) {
    int bh = blockIdx.x, tid = threadIdx.x;
    float w0 = w[0], w1 = wa[0], w2 = wp[0];
    size_t base = (size_t)bh * NS;
    __shared__ float red[256];
    float mx = -1e30f;
    for (int j = tid; j < NWN; j += 256) {
        float z = w0 * g_tn[base + j] + w1 * g_d2[base + j] + w2 * g_d3[base + j];
        g_attn[base + j] = z;
        mx = fmaxf(mx, z);
    }
    red[tid] = mx; __syncthreads();
    for (int o = 128; o; o >>= 1) { if (tid < o) red[tid] = fmaxf(red[tid], red[tid + o]); __syncthreads(); }
    mx = red[0]; __syncthreads();
    float sum = 0.f;
    for (int j = tid; j < NWN; j += 256) {
        float e = __expf(g_attn[base + j] - mx);
        g_attn[base + j] = e;
        sum += e;
    }
    red[tid] = sum; __syncthreads();
    for (int o = 128; o; o >>= 1) { if (tid < o) red[tid] += red[tid + o]; __syncthreads(); }
    float inv = 1.f / red[0];
    __syncthreads();
    for (int j = tid; j < NWN; j += 256) g_attn[base + j] *= inv;
    __syncthreads();
    if (tid == 0) g_alast[bh] = g_attn[base + NWN - 1];
}

// ---- ctx partial: grid(24,8), 512 thr, constant-trip unrolled loops ----
__global__ void __launch_bounds__(512) ctxp_kernel(const float* __restrict__ mem) {
    int wc = blockIdx.x, b = blockIdx.y, tid = threadIdx.x;
    __shared__ float at[8 * WWIN];
    int w0 = wc * WWIN;
    for (int u = tid; u < 8 * WWIN; u += 512) {
        int h = u >> 8, ww = u & (WWIN - 1);
        int w = w0 + ww;
        at[u] = (w < NWN - 1) ? g_attn[(size_t)(b * 8 + h) * NS + w] : 0.f;
    }
    __syncthreads();
    float acc[8] = {};
    const float* mb = mem + ((size_t)b * NSM1 + 31 + w0) * 512 + tid;
    if (wc < NWC - 1) {
#pragma unroll 8
        for (int ww = 0; ww < WWIN; ww++) {
            float x = mb[(size_t)ww * 512];
#pragma unroll
            for (int h2 = 0; h2 < 8; h2++) acc[h2] += at[h2 * WWIN + ww] * x;
        }
    } else {
        // last chunk: NWN-1 - 23*256 = 224 valid rows (constant)
#pragma unroll 8
        for (int ww = 0; ww < 224; ww++) {
            float x = mb[(size_t)ww * 512];
#pragma unroll
            for (int h2 = 0; h2 < 8; h2++) acc[h2] += at[h2 * WWIN + ww] * x;
        }
    }
#pragma unroll
    for (int h2 = 0; h2 < 8; h2++)
        g_ctxp[(((b * NWC + wc) * 8 + h2) << 9) + tid] = acc[h2];
}

// ---- hist : grid(8b,8h), 256 thr ----
__global__ void __launch_bounds__(256) hist_kernel(const float* __restrict__ bv) {
    int b = blockIdx.x, h = blockIdx.y, tid = threadIdx.x;
    __shared__ float ctxs[512];
    __shared__ float red[256];
    for (int d = tid; d < 512; d += 256) {
        float s = 0.f;
#pragma unroll
        for (int wc = 0; wc < NWC; wc++)
            s += g_ctxp[(((b * NWC + wc) * 8 + h) << 9) + d];
        ctxs[d] = s;
    }
    __syncthreads();
    int kk = tid >> 2, q = (tid & 3) * 128;
    const float* wr = g_WvM + (h * 64 + kk) * 512 + q;
    float acc = 0.f;
    for (int d = 0; d < 128; d += 4) {
        float4 wv = *(const float4*)(wr + d);
        acc += wv.x * ctxs[q + d] + wv.y * ctxs[q + d + 1] + wv.z * ctxs[q + d + 2] + wv.w * ctxs[q + d + 3];
    }
    red[tid] = acc;
    __syncthreads();
    if (tid < 64) {
        float a1 = 1.0f - g_alast[b * 8 + h];
        float s = red[tid * 4] + red[tid * 4 + 1] + red[tid * 4 + 2] + red[tid * 4 + 3];
        g_hist[(b * 8 + h) * 64 + tid] = s + bv[h * 64 + tid] * a1;
    }
}

// ---- GRU gi precompute : grid(31,8), 192 thr ----
__global__ void gi_kernel(const float* __restrict__ mem, const float* __restrict__ W_ih,
                          const float* __restrict__ b_ih) {
    int t = blockIdx.x, b = blockIdx.y, j = threadIdx.x;
    const float* xr = mem + ((size_t)b * NSM1 + 6112 + t) * 512;
    const float* wr = W_ih + j * 512;
    float acc = b_ih[j];
    for (int d = 0; d < 512; d += 4) {
        float4 xv = *(const float4*)(xr + d);
        float4 wv = *(const float4*)(wr + d);
        acc += xv.x * wv.x + xv.y * wv.y + xv.z * wv.z + xv.w * wv.w;
    }
    g_GI[(t * 8 + b) * 192 + j] = acc;
}

// ---- GRU scan : 1 block, 512 thr ----
__global__ void __launch_bounds__(512) scan_kernel(const float* __restrict__ W_hh,
                                                   const float* __restrict__ b_hh) {
    int tid = threadIdx.x;
    int b = tid >> 6, kk = tid & 63;
    __shared__ float hs[8 * 64];
    hs[tid] = 0.f;
    __syncthreads();
    float bhr = b_hh[kk], bhz = b_hh[64 + kk], bhn = b_hh[128 + kk];
    const float* wr = W_hh + kk * 64;
    const float* wz = W_hh + (64 + kk) * 64;
    const float* wn = W_hh + (128 + kk) * 64;
    for (int t = 0; t < 31; t++) {
        float hr = bhr, hz = bhz, hn = bhn;
        const float* hb = hs + b * 64;
#pragma unroll 8
        for (int e = 0; e < 64; e++) {
            float he = hb[e];
            hr += wr[e] * he; hz += wz[e] * he; hn += wn[e] * he;
        }
        const float* gi = g_GI + (t * 8 + b) * 192;
        float r = 1.f / (1.f + __expf(-(gi[kk] + hr)));
        float z = 1.f / (1.f + __expf(-(gi[64 + kk] + hz)));
        float nst = tanhf(gi[128 + kk] + r * hn);
        float hold = hb[kk];
        float hnew = (1.f - z) * nst + z * hold;
        __syncthreads();
        hs[tid] = hnew;
        __syncthreads();
    }
    g_res[tid] = hs[tid];
}

// ---- final output : grid(8), 512 thr ----
__global__ void __launch_bounds__(512) final_kernel(const float* __restrict__ xpre,
                                                    const float* __restrict__ bO,
                                                    float* __restrict__ out) {
    int b = blockIdx.x, tid = threadIdx.x;
    __shared__ float det[512];
    {
        int h = tid >> 6, kk = tid & 63;
        det[tid] = g_hist[(b * 8 + h) * 64 + kk] + g_alast[b * 8 + h] * g_res[b * 64 + kk];
    }
    __syncthreads();
    float acc = 0.f;
#pragma unroll 8
    for (int e = 0; e < 512; e++) acc += det[e] * g_WOMt[e * 512 + tid];
    out[b * 512 + tid] = xpre[b * 512 + tid] + acc + bO[tid];
}

extern "C" void kernel_launch(void* const* d_in, const int* in_sizes, int n_in,
                              void* d_out, int out_size) {
    const float* mem  = (const float*)d_in[0];
    const float* xpre = (const float*)d_in[1];
    const float* aux  = (const float*)d_in[2];
    const float* pos  = (const float*)d_in[3];
    const float* Wq   = (const float*)d_in[4];
    const float* bq   = (const float*)d_in[5];
    const float* Wk   = (const float*)d_in[6];
    const float* bk   = (const float*)d_in[7];
    const float* Wv   = (const float*)d_in[8];
    const float* bv   = (const float*)d_in[9];
    const float* Wqa  = (const float*)d_in[10];
    const float* bqa  = (const float*)d_in[11];
    const float* Wka  = (const float*)d_in[12];
    const float* bka  = (const float*)d_in[13];
    const float* Wqp  = (const float*)d_in[14];
    const float* bqp  = (const float*)d_in[15];
    const float* Wkp  = (const float*)d_in[16];
    const float* bkp  = (const float*)d_in[17];
    const float* W_ih = (const float*)d_in[18];
    const float* W_hh = (const float*)d_in[19];
    const float* b_ih = (const float*)d_in[20];
    const float* b_hh = (const float*)d_in[21];
    const float* WO   = (const float*)d_in[22];
    const float* bO   = (const float*)d_in[23];
    const float* w    = (const float*)d_in[24];
    const float* wa   = (const float*)d_in[25];
    const float* wp   = (const float*)d_in[26];
    const int*   G    = (const int*)d_in[27];
    float* out = (float*)d_out;

    // Order chosen so the ncu single-capture (4th launch) lands on dot2_kernel.
    prep_kernel<<<(512 * 512 + 255) / 256, 256>>>(Wk, Wq, Wv, WO, G);
    qa_kernel<<<8, 256>>>(aux, Wqa, bqa);
    kproj_kernel<<<dim3(48, 4, 8), 256>>>(mem, xpre, bk);
    dot2_kernel<<<dim3(48, 2, 8), 256>>>(aux, Wka, bka);
    qp_kernel<<<8, 128>>>(pos, Wqp, bqp);
    qproj_kernel<<<dim3(8, 8), 256>>>(mem, xpre, bq);
    tn_kernel<<<dim3(48, 8, 8), 128>>>();
    dot3_kernel<<<dim3(48, 1, 8), 256>>>(pos, Wkp, bkp);
    softmax_kernel<<<64, 256>>>(w, wa, wp);
    ctxp_kernel<<<dim3(NWC, 8), 512>>>(mem);
    hist_kernel<<<dim3(8, 8), 256>>>(bv);
    gi_kernel<<<dim3(31, 8), 192>>>(mem, W_ih, b_ih);
    scan_kernel<<<1, 512>>>(W_hh, b_hh);
    final_kernel<<<8, 512>>>(xpre, bO, out);
}

// round 13
// speedup vs baseline: 1.1189x; 1.1084x over previous
#include <cuda_runtime.h>
#include <cuda_bf16.h>
#include <math.h>

#define NB 8
#define NH 8
#define NS 6144
#define NSM1 6143
#define NDM 512
#define NDK 64
#define NWN 6113
#define NM 32
#define NWC 24
#define WWIN 256

typedef unsigned int u32;
typedef unsigned long long u64;

__device__ float g_WqM[512 * 512];
__device__ float g_WvM[512 * 512];
__device__ float g_WOMt[512 * 512];
__device__ __nv_bfloat16 g_Wkhi[512 * 512];
__device__ __nv_bfloat16 g_Wklo[512 * 512];
__device__ float g_Khat[(size_t)NB * NH * NS * NDK];
__device__ float g_Qhat[NB * NH * NM * NDK];
__device__ float g_qa[NB * NH * 32];
__device__ float g_qp[NB * NH * 16];
__device__ float g_tn[(size_t)NB * NH * NS];
__device__ float g_d2[(size_t)NB * NH * NS];
__device__ float g_d3[(size_t)NB * NH * NS];
__device__ float g_attn[(size_t)NB * NH * NS];
__device__ float g_alast[NB * NH];
__device__ float g_ctxp[NB * NWC * NH * NDM];
__device__ float g_hist[NB * NH * NDK];
__device__ float g_GI[31 * NB * 192];
__device__ float g_res[NB * NDK];

__device__ __forceinline__ u32 smem_u32(const void* p) {
    u32 a;
    asm("{ .reg .u64 t; cvta.to.shared.u64 t, %1; cvt.u32.u64 %0, t; }" : "=r"(a) : "l"(p));
    return a;
}
__device__ __forceinline__ void ldmx4(u32& r0, u32& r1, u32& r2, u32& r3, u32 a) {
    asm volatile("ldmatrix.sync.aligned.m8n8.x4.shared.b16 {%0,%1,%2,%3}, [%4];"
                 : "=r"(r0), "=r"(r1), "=r"(r2), "=r"(r3) : "r"(a));
}
__device__ __forceinline__ void ldmx2(u32& r0, u32& r1, u32 a) {
    asm volatile("ldmatrix.sync.aligned.m8n8.x2.shared.b16 {%0,%1}, [%2];"
                 : "=r"(r0), "=r"(r1) : "r"(a));
}
__device__ __forceinline__ void mma16816(float* c, const u32* a, const u32* b) {
    asm volatile(
        "mma.sync.aligned.m16n8k16.row.col.f32.bf16.bf16.f32 "
        "{%0,%1,%2,%3}, {%4,%5,%6,%7}, {%8,%9}, {%0,%1,%2,%3};"
        : "+f"(c[0]), "+f"(c[1]), "+f"(c[2]), "+f"(c[3])
        : "r"(a[0]), "r"(a[1]), "r"(a[2]), "r"(a[3]), "r"(b[0]), "r"(b[1]));
}

// ---- masked weights (+ bf16 hi/lo split of Wk) ----
__global__ void prep_kernel(const float* __restrict__ Wk, const float* __restrict__ Wq,
                            const float* __restrict__ Wv, const float* __restrict__ WO,
                            const int* __restrict__ G) {
    int i = blockIdx.x * blockDim.x + threadIdx.x;
    if (i >= 512 * 512) return;
    int row = i >> 9, d = i & 511;
    float gm = (float)G[(row & 63) * 64 + (d & 63)];
    float mk = Wk[i] * gm;
    __nv_bfloat16 h = __float2bfloat16(mk);
    g_Wkhi[i] = h;
    g_Wklo[i] = __float2bfloat16(mk - __bfloat162float(h));
    g_WqM[i] = Wq[i] * gm;
    g_WvM[i] = Wv[i] * gm;
    float gm2 = (float)G[(d & 63) * 64 + (row & 63)];
    g_WOMt[i] = WO[d * 512 + row] * gm2;
}

// ---- K projection via mma.sync bf16 hi/lo x3 : grid(48,4,8), 256 thr ----
// Block tile 128(M) x 128(N=2 heads), K=512 in 16 chunks of 32.
#define STR 40   // smem row stride in halves (80B, conflict-free for ldmatrix)
__global__ void __launch_bounds__(256) kproj_mma_kernel(const float* __restrict__ mem,
                                                        const float* __restrict__ xpre,
                                                        const float* __restrict__ bk) {
    __shared__ __align__(16) char sm_raw[40960];   // AH|AL|BH|BL (mainloop) / Ct 64x136 f32 (epilogue)
    __shared__ float invs[128];
    __nv_bfloat16* AH = (__nv_bfloat16*)(sm_raw);
    __nv_bfloat16* AL = (__nv_bfloat16*)(sm_raw + 10240);
    __nv_bfloat16* BH = (__nv_bfloat16*)(sm_raw + 20480);
    __nv_bfloat16* BL = (__nv_bfloat16*)(sm_raw + 30720);
    float* Ct = (float*)sm_raw;
    u32 sb = smem_u32(sm_raw);
    int tid = threadIdx.x, wid = tid >> 5, lane = tid & 31;
    int warpM = wid & 3, warpN = wid >> 2;
    int s0 = blockIdx.x * 128, n0 = blockIdx.y * 128, b = blockIdx.z;
    int r = tid >> 1, hf = tid & 1;
    float C[2][8][4] = {};

    for (int ch = 0; ch < 16; ch++) {
        int d0 = ch * 32;
        __syncthreads();
        {   // A: 128 rows x 32 fp32 -> bf16 hi/lo
            int s = s0 + r;
            const float* src = (s < NSM1) ? (mem + ((size_t)b * NSM1 + s) * 512 + d0 + hf * 16)
                                          : (xpre + b * 512 + d0 + hf * 16);
            u32 hw[8], lw[8];
#pragma unroll
            for (int i = 0; i < 4; i++) {
                float4 v = *(const float4*)(src + i * 4);
                __nv_bfloat16 h0 = __float2bfloat16(v.x), h1 = __float2bfloat16(v.y);
                __nv_bfloat16 h2 = __float2bfloat16(v.z), h3 = __float2bfloat16(v.w);
                float l0 = v.x - __bfloat162float(h0), l1 = v.y - __bfloat162float(h1);
                float l2 = v.z - __bfloat162float(h2), l3 = v.w - __bfloat162float(h3);
                __nv_bfloat162 ph0(h0, h1), ph1(h2, h3);
                __nv_bfloat162 pl0(__float2bfloat16(l0), __float2bfloat16(l1));
                __nv_bfloat162 pl1(__float2bfloat16(l2), __float2bfloat16(l3));
                hw[2 * i] = *(u32*)&ph0; hw[2 * i + 1] = *(u32*)&ph1;
                lw[2 * i] = *(u32*)&pl0; lw[2 * i + 1] = *(u32*)&pl1;
            }
            int ho = r * STR + hf * 16;
            *(uint4*)(AH + ho) = make_uint4(hw[0], hw[1], hw[2], hw[3]);
            *(uint4*)(AH + ho + 8) = make_uint4(hw[4], hw[5], hw[6], hw[7]);
            *(uint4*)(AL + ho) = make_uint4(lw[0], lw[1], lw[2], lw[3]);
            *(uint4*)(AL + ho + 8) = make_uint4(lw[4], lw[5], lw[6], lw[7]);
            // B: 128 rows x 32 bf16 (pre-split hi/lo)
            const uint4* gh = (const uint4*)(g_Wkhi + (size_t)(n0 + r) * 512 + d0 + hf * 16);
            const uint4* gl = (const uint4*)(g_Wklo + (size_t)(n0 + r) * 512 + d0 + hf * 16);
            *(uint4*)(BH + ho) = gh[0]; *(uint4*)(BH + ho + 8) = gh[1];
            *(uint4*)(BL + ho) = gl[0]; *(uint4*)(BL + ho + 8) = gl[1];
        }
        __syncthreads();
#pragma unroll
        for (int ks = 0; ks < 2; ks++) {
            u32 ah[2][4], al[2][4];
#pragma unroll
            for (int i = 0; i < 2; i++) {
                u32 off = (u32)(((warpM * 32 + i * 16 + (lane & 15)) * STR + ks * 16 + (lane >> 4) * 8) * 2);
                ldmx4(ah[i][0], ah[i][1], ah[i][2], ah[i][3], sb + off);
                ldmx4(al[i][0], al[i][1], al[i][2], al[i][3], sb + 10240 + off);
            }
            u32 bh[8][2], bl[8][2];
#pragma unroll
            for (int j = 0; j < 8; j++) {
                u32 off = (u32)(((warpN * 64 + j * 8 + (lane & 7)) * STR + ks * 16 + ((lane >> 3) & 1) * 8) * 2);
                ldmx2(bh[j][0], bh[j][1], sb + 20480 + off);
                ldmx2(bl[j][0], bl[j][1], sb + 30720 + off);
            }
#pragma unroll
            for (int i = 0; i < 2; i++)
#pragma unroll
                for (int j = 0; j < 8; j++) {
                    mma16816(C[i][j], ah[i], bh[j]);
                    mma16816(C[i][j], ah[i], bl[j]);
                    mma16816(C[i][j], al[i], bh[j]);
                }
        }
    }

    int h0 = n0 >> 6;
    // epilogue in two 64-row halves (Ct = 64x136 fp32 reuses mainloop smem)
#pragma unroll
    for (int half = 0; half < 2; half++) {
        __syncthreads();
        if ((warpM >> 1) == half) {
            int wm = warpM & 1;
#pragma unroll
            for (int i = 0; i < 2; i++)
#pragma unroll
                for (int j = 0; j < 8; j++) {
                    int row0 = wm * 32 + i * 16 + (lane >> 2);
                    int col = warpN * 64 + j * 8 + (lane & 3) * 2;
                    float b0 = bk[n0 + col], b1 = bk[n0 + col + 1];
                    *(float2*)&Ct[row0 * 136 + col] = make_float2(C[i][j][0] + b0, C[i][j][1] + b1);
                    *(float2*)&Ct[(row0 + 8) * 136 + col] = make_float2(C[i][j][2] + b0, C[i][j][3] + b1);
                }
        }
        __syncthreads();
        if (tid < 128) {
            int rowL = tid >> 1, hh = tid & 1;
            const float* rp = Ct + rowL * 136 + hh * 64;
            float ss = 0.f;
#pragma unroll 8
            for (int c = 0; c < 64; c++) { float v = rp[c]; ss += v * v; }
            invs[tid] = 1.0f / fmaxf(sqrtf(ss), 1e-12f);
        }
        __syncthreads();
        {
            int c4 = (tid & 31) * 4;
            int head = c4 >> 6, col64 = c4 & 63;
#pragma unroll
            for (int rr = tid >> 5; rr < 64; rr += 8) {
                float4 v = *(float4*)&Ct[rr * 136 + c4];
                float inv = invs[rr * 2 + head];
                int srow = s0 + half * 64 + rr;
                float* dst = g_Khat + (((size_t)(b * 8 + h0 + head)) * NS + srow) * 64 + col64;
                *(float4*)dst = make_float4(v.x * inv, v.y * inv, v.z * inv, v.w * inv);
            }
        }
    }
}

// ---- Q projection (last 32 rows) : grid(8h,8b), 256 thr ----
__global__ void __launch_bounds__(256) qproj_kernel(const float* __restrict__ mem,
                                                    const float* __restrict__ xpre,
                                                    const float* __restrict__ bq) {
    int h = blockIdx.x, b = blockIdx.y, tid = threadIdx.x;
    int m = tid >> 3, cg = (tid & 7) * 8;
    float acc[8] = {};
    int s = 6112 + m;
    const float* xr = (s < NSM1) ? (mem + ((size_t)b * NSM1 + s) * 512) : (xpre + b * 512);
    const float* wb = g_WqM + (h * 64 + cg) * 512;
    for (int d = 0; d < 512; d += 4) {
        float4 xv = *(const float4*)(xr + d);
#pragma unroll
        for (int c = 0; c < 8; c++) {
            float4 wv = *(const float4*)(wb + c * 512 + d);
            acc[c] += xv.x * wv.x + xv.y * wv.y + xv.z * wv.z + xv.w * wv.w;
        }
    }
    __shared__ float qs[32 * 65];
#pragma unroll
    for (int c = 0; c < 8; c++) qs[m * 65 + cg + c] = acc[c] + bq[h * 64 + cg + c];
    __syncthreads();
    if (tid < 32) {
        float ss = 0.f;
        for (int c = 0; c < 64; c++) { float v = qs[tid * 65 + c]; ss += v * v; }
        float inv = 1.f / fmaxf(sqrtf(ss), 1e-12f);
        float* dst = g_Qhat + ((b * 8 + h) * 32 + tid) * 64;
        for (int c = 0; c < 64; c++) dst[c] = qs[tid * 65 + c] * inv;
    }
}

// ---- tn: banded correlation : grid(48,8,8), 128 thr ----
__global__ void __launch_bounds__(128) tn_kernel() {
    int j0 = blockIdx.x * 128, h = blockIdx.y, b = blockIdx.z;
    int bh = b * 8 + h, tid = threadIdx.x;
    __shared__ __align__(16) float qs[32 * 64];
    __shared__ __align__(16) float Ks[159 * 36];
    for (int u = tid; u < 512; u += 128)
        ((float4*)qs)[u] = ((const float4*)(g_Qhat + bh * 2048))[u];
    float acc = 0.f;
    const float* kb = g_Khat + (size_t)bh * NS * 64;
    for (int p = 0; p < 2; p++) {
        __syncthreads();
        for (int v = tid; v < 159 * 8; v += 128) {
            int u = v >> 3, c4 = (v & 7) * 4;
            int s = j0 + u;
            float4 val = make_float4(0.f, 0.f, 0.f, 0.f);
            if (s < NS) val = *(const float4*)(kb + (size_t)s * 64 + p * 32 + c4);
            *(float4*)&Ks[u * 36 + c4] = val;
        }
        __syncthreads();
#pragma unroll 4
        for (int m = 0; m < 32; m++) {
            const float* qrow = qs + m * 64 + p * 32;
            const float* krow = Ks + (tid + m) * 36;
#pragma unroll
            for (int c = 0; c < 8; c++) {
                float4 kv = *(const float4*)(krow + c * 4);
                float4 qv = *(const float4*)(qrow + c * 4);
                acc += qv.x * kv.x + qv.y * kv.y + qv.z * kv.z + qv.w * kv.w;
            }
        }
    }
    int j = j0 + tid;
    if (j < NWN) g_tn[(size_t)bh * NS + j] = acc * (1.0f / 32.0f);
}

// ---- qa_last, qp_last ----
__global__ void qa_kernel(const float* __restrict__ aux, const float* __restrict__ Wqa,
                          const float* __restrict__ bqa) {
    int b = blockIdx.x, tid = threadIdx.x;
    int h = tid >> 5, c = tid & 31;
    const float* row = aux + ((size_t)b * NS + NS - 1) * 256;
    const float* wr = Wqa + (h * 32 + c) * 256;
    float acc = bqa[h * 32 + c];
    for (int a = 0; a < 256; a += 4) {
        float4 xv = *(const float4*)(row + a);
        float4 wv = *(const float4*)(wr + a);
        acc += xv.x * wv.x + xv.y * wv.y + xv.z * wv.z + xv.w * wv.w;
    }
    float ss = acc * acc;
#pragma unroll
    for (int o = 16; o; o >>= 1) ss += __shfl_xor_sync(0xffffffffu, ss, o);
    g_qa[(b * 8 + h) * 32 + c] = acc / fmaxf(sqrtf(ss), 1e-12f);
}

__global__ void qp_kernel(const float* __restrict__ pos, const float* __restrict__ Wqp,
                          const float* __restrict__ bqp) {
    int b = blockIdx.x, tid = threadIdx.x;
    int h = tid >> 4, c = tid & 15;
    const float* row = pos + ((size_t)b * NS + NS - 1) * 128;
    const float* wr = Wqp + (h * 16 + c) * 128;
    float acc = bqp[h * 16 + c];
    for (int a = 0; a < 128; a += 4) {
        float4 xv = *(const float4*)(row + a);
        float4 wv = *(const float4*)(wr + a);
        acc += xv.x * wv.x + xv.y * wv.y + xv.z * wv.z + xv.w * wv.w;
    }
    float ss = acc * acc;
#pragma unroll
    for (int o = 8; o; o >>= 1) ss += __shfl_xor_sync(0xffffffffu, ss, o);
    g_qp[(b * 8 + h) * 16 + c] = acc / fmaxf(sqrtf(ss), 1e-12f);
}

// ---- dot2 batched: grid(48,2,8), 256 thr, 128x128 tile, K=256 ----
__global__ void __launch_bounds__(256) dot2_kernel(const float* __restrict__ aux,
                                                   const float* __restrict__ Wka,
                                                   const float* __restrict__ bka) {
    __shared__ __align__(16) float As[32 * 132];
    __shared__ __align__(16) float Bs[32 * 132];
    int j0 = blockIdx.x * 128, n0 = blockIdx.y * 128, b = blockIdx.z;
    int tid = threadIdx.x;
    int ty = tid >> 4, tx = tid & 15;
    float acc[8][8] = {};
    for (int d0 = 0; d0 < 256; d0 += 32) {
        __syncthreads();
#pragma unroll
        for (int it = 0; it < 4; it++) {
            int idx = it * 256 + tid;
            int rr = idx >> 3, kq = (idx & 7) * 4;
            int j = j0 + rr;
            float4 v = make_float4(0.f, 0.f, 0.f, 0.f);
            if (j < NWN) v = *(const float4*)(aux + ((size_t)b * NS + 31 + j) * 256 + d0 + kq);
            As[(kq + 0) * 132 + rr] = v.x; As[(kq + 1) * 132 + rr] = v.y;
            As[(kq + 2) * 132 + rr] = v.z; As[(kq + 3) * 132 + rr] = v.w;
            float4 wv = *(const float4*)(Wka + (size_t)(n0 + rr) * 256 + d0 + kq);
            Bs[(kq + 0) * 132 + rr] = wv.x; Bs[(kq + 1) * 132 + rr] = wv.y;
            Bs[(kq + 2) * 132 + rr] = wv.z; Bs[(kq + 3) * 132 + rr] = wv.w;
        }
        __syncthreads();
#pragma unroll
        for (int kk = 0; kk < 32; kk++) {
            float4 a0 = *(const float4*)&As[kk * 132 + ty * 4];
            float4 a1 = *(const float4*)&As[kk * 132 + 64 + ty * 4];
            float4 b0 = *(const float4*)&Bs[kk * 132 + tx * 4];
            float4 b1 = *(const float4*)&Bs[kk * 132 + 64 + tx * 4];
            float ar[8] = {a0.x, a0.y, a0.z, a0.w, a1.x, a1.y, a1.z, a1.w};
            float br[8] = {b0.x, b0.y, b0.z, b0.w, b1.x, b1.y, b1.z, b1.w};
#pragma unroll
            for (int i = 0; i < 8; i++)
#pragma unroll
                for (int j = 0; j < 8; j++) acc[i][j] += ar[i] * br[j];
        }
    }
    int hA = (n0 >> 5) + (tx >> 3);
    int hB = hA + 2;
    const float* qaA = g_qa + (b * 8 + hA) * 32;
    const float* qaB = g_qa + (b * 8 + hB) * 32;
    float biasA[4], biasB[4];
#pragma unroll
    for (int j = 0; j < 4; j++) {
        biasA[j] = bka[n0 + tx * 4 + j];
        biasB[j] = bka[n0 + 64 + tx * 4 + j];
    }
    int c32 = (tx & 7) * 4;
#pragma unroll
    for (int i = 0; i < 8; i++) {
        int r = (i < 4) ? (ty * 4 + i) : (64 + ty * 4 + (i - 4));
        int jrow = j0 + r;
        float ss0 = 0.f, dt0 = 0.f, ss1 = 0.f, dt1 = 0.f;
#pragma unroll
        for (int j = 0; j < 4; j++) {
            float v0 = acc[i][j] + biasA[j];
            float v1 = acc[i][4 + j] + biasB[j];
            ss0 += v0 * v0; dt0 += qaA[c32 + j] * v0;
            ss1 += v1 * v1; dt1 += qaB[c32 + j] * v1;
        }
#pragma unroll
        for (int o = 1; o < 8; o <<= 1) {
            ss0 += __shfl_xor_sync(0xffffffffu, ss0, o);
            dt0 += __shfl_xor_sync(0xffffffffu, dt0, o);
            ss1 += __shfl_xor_sync(0xffffffffu, ss1, o);
            dt1 += __shfl_xor_sync(0xffffffffu, dt1, o);
        }
        if ((tx & 7) == 0 && jrow < NWN) {
            g_d2[(size_t)(b * 8 + hA) * NS + jrow] = dt0 / fmaxf(sqrtf(ss0), 1e-12f);
            g_d2[(size_t)(b * 8 + hB) * NS + jrow] = dt1 / fmaxf(sqrtf(ss1), 1e-12f);
        }
    }
}

// ---- dot3 batched: grid(48,1,8), 256 thr, 128x128, K=128 ----
__global__ void __launch_bounds__(256) dot3_kernel(const float* __restrict__ pos,
                                                   const float* __restrict__ Wkp,
                                                   const float* __restrict__ bkp) {
    __shared__ __align__(16) float As[32 * 132];
    __shared__ __align__(16) float Bs[32 * 132];
    int j0 = blockIdx.x * 128, b = blockIdx.z;
    int tid = threadIdx.x;
    int ty = tid >> 4, tx = tid & 15;
    float acc[8][8] = {};
    for (int d0 = 0; d0 < 128; d0 += 32) {
        __syncthreads();
#pragma unroll
        for (int it = 0; it < 4; it++) {
            int idx = it * 256 + tid;
            int rr = idx >> 3, kq = (idx & 7) * 4;
            int j = j0 + rr;
            float4 v = make_float4(0.f, 0.f, 0.f, 0.f);
            if (j < NWN) v = *(const float4*)(pos + ((size_t)b * NS + 31 + j) * 128 + d0 + kq);
            As[(kq + 0) * 132 + rr] = v.x; As[(kq + 1) * 132 + rr] = v.y;
            As[(kq + 2) * 132 + rr] = v.z; As[(kq + 3) * 132 + rr] = v.w;
            float4 wv = *(const float4*)(Wkp + (size_t)rr * 128 + d0 + kq);
            Bs[(kq + 0) * 132 + rr] = wv.x; Bs[(kq + 1) * 132 + rr] = wv.y;
            Bs[(kq + 2) * 132 + rr] = wv.z; Bs[(kq + 3) * 132 + rr] = wv.w;
        }
        __syncthreads();
#pragma unroll
        for (int kk = 0; kk < 32; kk++) {
            float4 a0 = *(const float4*)&As[kk * 132 + ty * 4];
            float4 a1 = *(const float4*)&As[kk * 132 + 64 + ty * 4];
            float4 b0 = *(const float4*)&Bs[kk * 132 + tx * 4];
            float4 b1 = *(const float4*)&Bs[kk * 132 + 64 + tx * 4];
            float ar[8] = {a0.x, a0.y, a0.z, a0.w, a1.x, a1.y, a1.z, a1.w};
            float br[8] = {b0.x, b0.y, b0.z, b0.w, b1.x, b1.y, b1.z, b1.w};
#pragma unroll
            for (int i = 0; i < 8; i++)
#pragma unroll
                for (int j = 0; j < 8; j++) acc[i][j] += ar[i] * br[j];
        }
    }
    int hA = tx >> 2;
    int hB = hA + 4;
    const float* qpA = g_qp + (b * 8 + hA) * 16;
    const float* qpB = g_qp + (b * 8 + hB) * 16;
    float biasA[4], biasB[4];
#pragma unroll
    for (int j = 0; j < 4; j++) {
        biasA[j] = bkp[tx * 4 + j];
        biasB[j] = bkp[64 + tx * 4 + j];
    }
    int c16 = (tx & 3) * 4;
#pragma unroll
    for (int i = 0; i < 8; i++) {
        int r = (i < 4) ? (ty * 4 + i) : (64 + ty * 4 + (i - 4));
        int jrow = j0 + r;
        float ss0 = 0.f, dt0 = 0.f, ss1 = 0.f, dt1 = 0.f;
#pragma unroll
        for (int j = 0; j < 4; j++) {
            float v0 = acc[i][j] + biasA[j];
            float v1 = acc[i][4 + j] + biasB[j];
            ss0 += v0 * v0; dt0 += qpA[c16 + j] * v0;
            ss1 += v1 * v1; dt1 += qpB[c16 + j] * v1;
        }
#pragma unroll
        for (int o = 1; o < 4; o <<= 1) {
            ss0 += __shfl_xor_sync(0xffffffffu, ss0, o);
            dt0 += __shfl_xor_sync(0xffffffffu, dt0, o);
            ss1 += __shfl_xor_sync(0xffffffffu, ss1, o);
            dt1 += __shfl_xor_sync(0xffffffffu, dt1, o);
        }
        if ((tx & 3) == 0 && jrow < NWN) {
            g_d3[(size_t)(b * 8 + hA) * NS + jrow] = dt0 / fmaxf(sqrtf(ss0), 1e-12f);
            g_d3[(size_t)(b * 8 + hB) * NS + jrow] = dt1 / fmaxf(sqrtf(ss1), 1e-12f);
        }
    }
}

// ---- softmax over Wn : grid(64), 256 thr ----
__global__ void __launch_bounds__(256) softmax_kernel(const float* __restrict__ w,
                                                      const float* __restrict__ wa,
                                                      const float* __restrict__ wp) {
    int bh = blockIdx.x, tid = threadIdx.x;
    float w0 = w[0], w1 = wa[0], w2 = wp[0];
    size_t base = (size_t)bh * NS;
    __shared__ float red[256];
    float mx = -1e30f;
    for (int j = tid; j < NWN; j += 256) {
        float z = w0 * g_tn[base + j] + w1 * g_d2[base + j] + w2 * g_d3[base + j];
        g_attn[base + j] = z;
        mx = fmaxf(mx, z);
    }
    red[tid] = mx; __syncthreads();
    for (int o = 128; o; o >>= 1) { if (tid < o) red[tid] = fmaxf(red[tid], red[tid + o]); __syncthreads(); }
    mx = red[0]; __syncthreads();
    float sum = 0.f;
    for (int j = tid; j < NWN; j += 256) {
        float e = __expf(g_attn[base + j] - mx);
        g_attn[base + j] = e;
        sum += e;
    }
    red[tid] = sum; __syncthreads();
    for (int o = 128; o; o >>= 1) { if (tid < o) red[tid] += red[tid + o]; __syncthreads(); }
    float inv = 1.f / red[0];
    __syncthreads();
    for (int j = tid; j < NWN; j += 256) g_attn[base + j] *= inv;
    __syncthreads();
    if (tid == 0) g_alast[bh] = g_attn[base + NWN - 1];
}

// ---- ctx partial: grid(24,8), 512 thr ----
__global__ void __launch_bounds__(512) ctxp_kernel(const float* __restrict__ mem) {
    int wc = blockIdx.x, b = blockIdx.y, tid = threadIdx.x;
    __shared__ float at[8 * WWIN];
    int w0 = wc * WWIN;
    for (int u = tid; u < 8 * WWIN; u += 512) {
        int h = u >> 8, ww = u & (WWIN - 1);
        int w = w0 + ww;
        at[u] = (w < NWN - 1) ? g_attn[(size_t)(b * 8 + h) * NS + w] : 0.f;
    }
    __syncthreads();
    float acc[8] = {};
    const float* mb = mem + ((size_t)b * NSM1 + 31 + w0) * 512 + tid;
    if (wc < NWC - 1) {
#pragma unroll 8
        for (int ww = 0; ww < WWIN; ww++) {
            float x = mb[(size_t)ww * 512];
#pragma unroll
            for (int h2 = 0; h2 < 8; h2++) acc[h2] += at[h2 * WWIN + ww] * x;
        }
    } else {
#pragma unroll 8
        for (int ww = 0; ww < 224; ww++) {
            float x = mb[(size_t)ww * 512];
#pragma unroll
            for (int h2 = 0; h2 < 8; h2++) acc[h2] += at[h2 * WWIN + ww] * x;
        }
    }
#pragma unroll
    for (int h2 = 0; h2 < 8; h2++)
        g_ctxp[(((b * NWC + wc) * 8 + h2) << 9) + tid] = acc[h2];
}

// ---- hist : grid(8b,8h), 256 thr ----
__global__ void __launch_bounds__(256) hist_kernel(const float* __restrict__ bv) {
    int b = blockIdx.x, h = blockIdx.y, tid = threadIdx.x;
    __shared__ float ctxs[512];
    __shared__ float red[256];
    for (int d = tid; d < 512; d += 256) {
        float s = 0.f;
#pragma unroll
        for (int wc = 0; wc < NWC; wc++)
            s += g_ctxp[(((b * NWC + wc) * 8 + h) << 9) + d];
        ctxs[d] = s;
    }
    __syncthreads();
    int kk = tid >> 2, q = (tid & 3) * 128;
    const float* wr = g_WvM + (h * 64 + kk) * 512 + q;
    float acc = 0.f;
    for (int d = 0; d < 128; d += 4) {
        float4 wv = *(const float4*)(wr + d);
        acc += wv.x * ctxs[q + d] + wv.y * ctxs[q + d + 1] + wv.z * ctxs[q + d + 2] + wv.w * ctxs[q + d + 3];
    }
    red[tid] = acc;
    __syncthreads();
    if (tid < 64) {
        float a1 = 1.0f - g_alast[b * 8 + h];
        float s = red[tid * 4] + red[tid * 4 + 1] + red[tid * 4 + 2] + red[tid * 4 + 3];
        g_hist[(b * 8 + h) * 64 + tid] = s + bv[h * 64 + tid] * a1;
    }
}

// ---- GRU gi precompute : grid(31,8), 192 thr ----
__global__ void gi_kernel(const float* __restrict__ mem, const float* __restrict__ W_ih,
                          const float* __restrict__ b_ih) {
    int t = blockIdx.x, b = blockIdx.y, j = threadIdx.x;
    const float* xr = mem + ((size_t)b * NSM1 + 6112 + t) * 512;
    const float* wr = W_ih + j * 512;
    float acc = b_ih[j];
    for (int d = 0; d < 512; d += 4) {
        float4 xv = *(const float4*)(xr + d);
        float4 wv = *(const float4*)(wr + d);
        acc += xv.x * wv.x + xv.y * wv.y + xv.z * wv.z + xv.w * wv.w;
    }
    g_GI[(t * 8 + b) * 192 + j] = acc;
}

// ---- GRU scan : 1 block, 512 thr ----
__global__ void __launch_bounds__(512) scan_kernel(const float* __restrict__ W_hh,
                                                   const float* __restrict__ b_hh) {
    int tid = threadIdx.x;
    int b = tid >> 6, kk = tid & 63;
    __shared__ float hs[8 * 64];
    hs[tid] = 0.f;
    __syncthreads();
    float bhr = b_hh[kk], bhz = b_hh[64 + kk], bhn = b_hh[128 + kk];
    const float* wr = W_hh + kk * 64;
    const float* wz = W_hh + (64 + kk) * 64;
    const float* wn = W_hh + (128 + kk) * 64;
    for (int t = 0; t < 31; t++) {
        float hr = bhr, hz = bhz, hn = bhn;
        const float* hb = hs + b * 64;
#pragma unroll 8
        for (int e = 0; e < 64; e++) {
            float he = hb[e];
            hr += wr[e] * he; hz += wz[e] * he; hn += wn[e] * he;
        }
        const float* gi = g_GI + (t * 8 + b) * 192;
        float r = 1.f / (1.f + __expf(-(gi[kk] + hr)));
        float z = 1.f / (1.f + __expf(-(gi[64 + kk] + hz)));
        float nst = tanhf(gi[128 + kk] + r * hn);
        float hold = hb[kk];
        float hnew = (1.f - z) * nst + z * hold;
        __syncthreads();
        hs[tid] = hnew;
        __syncthreads();
    }
    g_res[tid] = hs[tid];
}

// ---- final output : grid(8), 512 thr ----
__global__ void __launch_bounds__(512) final_kernel(const float* __restrict__ xpre,
                                                    const float* __restrict__ bO,
                                                    float* __restrict__ out) {
    int b = blockIdx.x, tid = threadIdx.x;
    __shared__ float det[512];
    {
        int h = tid >> 6, kk = tid & 63;
        det[tid] = g_hist[(b * 8 + h) * 64 + kk] + g_alast[b * 8 + h] * g_res[b * 64 + kk];
    }
    __syncthreads();
    float acc = 0.f;
#pragma unroll 8
    for (int e = 0; e < 512; e++) acc += det[e] * g_WOMt[e * 512 + tid];
    out[b * 512 + tid] = xpre[b * 512 + tid] + acc + bO[tid];
}

extern "C" void kernel_launch(void* const* d_in, const int* in_sizes, int n_in,
                              void* d_out, int out_size) {
    const float* mem  = (const float*)d_in[0];
    const float* xpre = (const float*)d_in[1];
    const float* aux  = (const float*)d_in[2];
    const float* pos  = (const float*)d_in[3];
    const float* Wq   = (const float*)d_in[4];
    const float* bq   = (const float*)d_in[5];
    const float* Wk   = (const float*)d_in[6];
    const float* bk   = (const float*)d_in[7];
    const float* Wv   = (const float*)d_in[8];
    const float* bv   = (const float*)d_in[9];
    const float* Wqa  = (const float*)d_in[10];
    const float* bqa  = (const float*)d_in[11];
    const float* Wka  = (const float*)d_in[12];
    const float* bka  = (const float*)d_in[13];
    const float* Wqp  = (const float*)d_in[14];
    const float* bqp  = (const float*)d_in[15];
    const float* Wkp  = (const float*)d_in[16];
    const float* bkp  = (const float*)d_in[17];
    const float* W_ih = (const float*)d_in[18];
    const float* W_hh = (const float*)d_in[19];
    const float* b_ih = (const float*)d_in[20];
    const float* b_hh = (const float*)d_in[21];
    const float* WO   = (const float*)d_in[22];
    const float* bO   = (const float*)d_in[23];
    const float* w    = (const float*)d_in[24];
    const float* wa   = (const float*)d_in[25];
    const float* wp   = (const float*)d_in[26];
    const int*   G    = (const int*)d_in[27];
    float* out = (float*)d_out;

    // 4th launch = kproj_mma_kernel (ncu capture target)
    prep_kernel<<<(512 * 512 + 255) / 256, 256>>>(Wk, Wq, Wv, WO, G);
    qa_kernel<<<8, 256>>>(aux, Wqa, bqa);
    qp_kernel<<<8, 128>>>(pos, Wqp, bqp);
    kproj_mma_kernel<<<dim3(48, 4, 8), 256>>>(mem, xpre, bk);
    qproj_kernel<<<dim3(8, 8), 256>>>(mem, xpre, bq);
    dot2_kernel<<<dim3(48, 2, 8), 256>>>(aux, Wka, bka);
    tn_kernel<<<dim3(48, 8, 8), 128>>>();
    dot3_kernel<<<dim3(48, 1, 8), 256>>>(pos, Wkp, bkp);
    softmax_kernel<<<64, 256>>>(w, wa, wp);
    ctxp_kernel<<<dim3(NWC, 8), 512>>>(mem);
    hist_kernel<<<dim3(8, 8), 256>>>(bv);
    gi_kernel<<<dim3(31, 8), 192>>>(mem, W_ih, b_ih);
    scan_kernel<<<1, 512>>>(W_hh, b_hh);
    final_kernel<<<8, 512>>>(xpre, bO, out);
}

// round 14
// speedup vs baseline: 1.1495x; 1.0273x over previous
#include <cuda_runtime.h>
#include <cuda_bf16.h>
#include <math.h>

#define NB 8
#define NH 8
#define NS 6144
#define NSM1 6143
#define NDM 512
#define NDK 64
#define NWN 6113
#define NM 32
#define NWC 24
#define WWIN 256

typedef unsigned int u32;
typedef unsigned long long u64;

__device__ float g_WqM[512 * 512];
__device__ float g_WvM[512 * 512];
__device__ float g_WOMt[512 * 512];
__device__ __nv_bfloat16 g_Wkhi[512 * 512];
__device__ __nv_bfloat16 g_Wklo[512 * 512];
__device__ __nv_bfloat16 g_Wkahi[256 * 256];
__device__ __nv_bfloat16 g_Wkalo[256 * 256];
__device__ __nv_bfloat16 g_Wkphi[128 * 128];
__device__ __nv_bfloat16 g_Wkplo[128 * 128];
__device__ float g_Khat[(size_t)NB * NH * NS * NDK];
__device__ float g_Qhat[NB * NH * NM * NDK];
__device__ float g_qa[NB * NH * 32];
__device__ float g_qp[NB * NH * 16];
__device__ float g_tn[(size_t)NB * NH * NS];
__device__ float g_d2[(size_t)NB * NH * NS];
__device__ float g_d3[(size_t)NB * NH * NS];
__device__ float g_attn[(size_t)NB * NH * NS];
__device__ float g_alast[NB * NH];
__device__ float g_ctxp[NB * NWC * NH * NDM];
__device__ float g_hist[NB * NH * NDK];
__device__ float g_GI[31 * NB * 192];
__device__ float g_res[NB * NDK];

__device__ __forceinline__ u32 smem_u32(const void* p) {
    u32 a;
    asm("{ .reg .u64 t; cvta.to.shared.u64 t, %1; cvt.u32.u64 %0, t; }" : "=r"(a) : "l"(p));
    return a;
}
__device__ __forceinline__ void ldmx4(u32& r0, u32& r1, u32& r2, u32& r3, u32 a) {
    asm volatile("ldmatrix.sync.aligned.m8n8.x4.shared.b16 {%0,%1,%2,%3}, [%4];"
                 : "=r"(r0), "=r"(r1), "=r"(r2), "=r"(r3) : "r"(a));
}
__device__ __forceinline__ void ldmx2(u32& r0, u32& r1, u32 a) {
    asm volatile("ldmatrix.sync.aligned.m8n8.x2.shared.b16 {%0,%1}, [%2];"
                 : "=r"(r0), "=r"(r1) : "r"(a));
}
__device__ __forceinline__ void mma16816(float* c, const u32* a, const u32* b) {
    asm volatile(
        "mma.sync.aligned.m16n8k16.row.col.f32.bf16.bf16.f32 "
        "{%0,%1,%2,%3}, {%4,%5,%6,%7}, {%8,%9}, {%0,%1,%2,%3};"
        : "+f"(c[0]), "+f"(c[1]), "+f"(c[2]), "+f"(c[3])
        : "r"(a[0]), "r"(a[1]), "r"(a[2]), "r"(a[3]), "r"(b[0]), "r"(b[1]));
}
__device__ __forceinline__ void split2(float4 v, u32* hw, u32* lw) {
    __nv_bfloat16 h0 = __float2bfloat16(v.x), h1 = __float2bfloat16(v.y);
    __nv_bfloat16 h2 = __float2bfloat16(v.z), h3 = __float2bfloat16(v.w);
    float l0 = v.x - __bfloat162float(h0), l1 = v.y - __bfloat162float(h1);
    float l2 = v.z - __bfloat162float(h2), l3 = v.w - __bfloat162float(h3);
    __nv_bfloat162 ph0(h0, h1), ph1(h2, h3);
    __nv_bfloat162 pl0(__float2bfloat16(l0), __float2bfloat16(l1));
    __nv_bfloat162 pl1(__float2bfloat16(l2), __float2bfloat16(l3));
    hw[0] = *(u32*)&ph0; hw[1] = *(u32*)&ph1;
    lw[0] = *(u32*)&pl0; lw[1] = *(u32*)&pl1;
}

// ---- masked weights + hi/lo splits ----
__global__ void prep_kernel(const float* __restrict__ Wk, const float* __restrict__ Wq,
                            const float* __restrict__ Wv, const float* __restrict__ WO,
                            const float* __restrict__ Wka, const float* __restrict__ Wkp,
                            const int* __restrict__ G) {
    int i = blockIdx.x * blockDim.x + threadIdx.x;
    if (i < 512 * 512) {
        int row = i >> 9, d = i & 511;
        float gm = (float)G[(row & 63) * 64 + (d & 63)];
        float mk = Wk[i] * gm;
        __nv_bfloat16 h = __float2bfloat16(mk);
        g_Wkhi[i] = h;
        g_Wklo[i] = __float2bfloat16(mk - __bfloat162float(h));
        g_WqM[i] = Wq[i] * gm;
        g_WvM[i] = Wv[i] * gm;
        float gm2 = (float)G[(d & 63) * 64 + (row & 63)];
        g_WOMt[i] = WO[d * 512 + row] * gm2;
    }
    if (i < 256 * 256) {
        float v = Wka[i];
        __nv_bfloat16 h = __float2bfloat16(v);
        g_Wkahi[i] = h;
        g_Wkalo[i] = __float2bfloat16(v - __bfloat162float(h));
    }
    if (i < 128 * 128) {
        float v = Wkp[i];
        __nv_bfloat16 h = __float2bfloat16(v);
        g_Wkphi[i] = h;
        g_Wkplo[i] = __float2bfloat16(v - __bfloat162float(h));
    }
}

#define STR 40   // smem row stride in halves (80B, conflict-free for ldmatrix)

// ---- K projection via mma.sync bf16 hi/lo x3 : grid(48,4,8), 256 thr ----
__global__ void __launch_bounds__(256) kproj_mma_kernel(const float* __restrict__ mem,
                                                        const float* __restrict__ xpre,
                                                        const float* __restrict__ bk) {
    __shared__ __align__(16) char sm_raw[40960];
    __shared__ float invs[128];
    __nv_bfloat16* AH = (__nv_bfloat16*)(sm_raw);
    __nv_bfloat16* AL = (__nv_bfloat16*)(sm_raw + 10240);
    __nv_bfloat16* BH = (__nv_bfloat16*)(sm_raw + 20480);
    __nv_bfloat16* BL = (__nv_bfloat16*)(sm_raw + 30720);
    float* Ct = (float*)sm_raw;
    u32 sb = smem_u32(sm_raw);
    int tid = threadIdx.x, wid = tid >> 5, lane = tid & 31;
    int warpM = wid & 3, warpN = wid >> 2;
    int s0 = blockIdx.x * 128, n0 = blockIdx.y * 128, b = blockIdx.z;
    int r = tid >> 1, hf = tid & 1;
    float C[2][8][4] = {};

    for (int ch = 0; ch < 16; ch++) {
        int d0 = ch * 32;
        __syncthreads();
        {
            int s = s0 + r;
            const float* src = (s < NSM1) ? (mem + ((size_t)b * NSM1 + s) * 512 + d0 + hf * 16)
                                          : (xpre + b * 512 + d0 + hf * 16);
            u32 hw[8], lw[8];
#pragma unroll
            for (int i = 0; i < 4; i++)
                split2(*(const float4*)(src + i * 4), hw + 2 * i, lw + 2 * i);
            int ho = r * STR + hf * 16;
            *(uint4*)(AH + ho) = make_uint4(hw[0], hw[1], hw[2], hw[3]);
            *(uint4*)(AH + ho + 8) = make_uint4(hw[4], hw[5], hw[6], hw[7]);
            *(uint4*)(AL + ho) = make_uint4(lw[0], lw[1], lw[2], lw[3]);
            *(uint4*)(AL + ho + 8) = make_uint4(lw[4], lw[5], lw[6], lw[7]);
            const uint4* gh = (const uint4*)(g_Wkhi + (size_t)(n0 + r) * 512 + d0 + hf * 16);
            const uint4* gl = (const uint4*)(g_Wklo + (size_t)(n0 + r) * 512 + d0 + hf * 16);
            *(uint4*)(BH + ho) = gh[0]; *(uint4*)(BH + ho + 8) = gh[1];
            *(uint4*)(BL + ho) = gl[0]; *(uint4*)(BL + ho + 8) = gl[1];
        }
        __syncthreads();
#pragma unroll
        for (int ks = 0; ks < 2; ks++) {
            u32 ah[2][4], al[2][4];
#pragma unroll
            for (int i = 0; i < 2; i++) {
                u32 off = (u32)(((warpM * 32 + i * 16 + (lane & 15)) * STR + ks * 16 + (lane >> 4) * 8) * 2);
                ldmx4(ah[i][0], ah[i][1], ah[i][2], ah[i][3], sb + off);
                ldmx4(al[i][0], al[i][1], al[i][2], al[i][3], sb + 10240 + off);
            }
            u32 bh[8][2], bl[8][2];
#pragma unroll
            for (int j = 0; j < 8; j++) {
                u32 off = (u32)(((warpN * 64 + j * 8 + (lane & 7)) * STR + ks * 16 + ((lane >> 3) & 1) * 8) * 2);
                ldmx2(bh[j][0], bh[j][1], sb + 20480 + off);
                ldmx2(bl[j][0], bl[j][1], sb + 30720 + off);
            }
#pragma unroll
            for (int i = 0; i < 2; i++)
#pragma unroll
                for (int j = 0; j < 8; j++) {
                    mma16816(C[i][j], ah[i], bh[j]);
                    mma16816(C[i][j], ah[i], bl[j]);
                    mma16816(C[i][j], al[i], bh[j]);
                }
        }
    }

    int h0 = n0 >> 6;
#pragma unroll
    for (int half = 0; half < 2; half++) {
        __syncthreads();
        if ((warpM >> 1) == half) {
            int wm = warpM & 1;
#pragma unroll
            for (int i = 0; i < 2; i++)
#pragma unroll
                for (int j = 0; j < 8; j++) {
                    int row0 = wm * 32 + i * 16 + (lane >> 2);
                    int col = warpN * 64 + j * 8 + (lane & 3) * 2;
                    float b0 = bk[n0 + col], b1 = bk[n0 + col + 1];
                    *(float2*)&Ct[row0 * 136 + col] = make_float2(C[i][j][0] + b0, C[i][j][1] + b1);
                    *(float2*)&Ct[(row0 + 8) * 136 + col] = make_float2(C[i][j][2] + b0, C[i][j][3] + b1);
                }
        }
        __syncthreads();
        if (tid < 128) {
            int rowL = tid >> 1, hh = tid & 1;
            const float* rp = Ct + rowL * 136 + hh * 64;
            float ss = 0.f;
#pragma unroll 8
            for (int c = 0; c < 64; c++) { float v = rp[c]; ss += v * v; }
            invs[tid] = 1.0f / fmaxf(sqrtf(ss), 1e-12f);
        }
        __syncthreads();
        {
            int c4 = (tid & 31) * 4;
            int head = c4 >> 6, col64 = c4 & 63;
#pragma unroll
            for (int rr = tid >> 5; rr < 64; rr += 8) {
                float4 v = *(float4*)&Ct[rr * 136 + c4];
                float inv = invs[rr * 2 + head];
                int srow = s0 + half * 64 + rr;
                float* dst = g_Khat + (((size_t)(b * 8 + h0 + head)) * NS + srow) * 64 + col64;
                *(float4*)dst = make_float4(v.x * inv, v.y * inv, v.z * inv, v.w * inv);
            }
        }
    }
}

// ---- dot2 via mma.sync : grid(48,2,8), 256 thr, 128x128 tile, K=256 ----
__global__ void __launch_bounds__(256) dot2_mma_kernel(const float* __restrict__ aux,
                                                       const float* __restrict__ bka) {
    __shared__ __align__(16) char sm_raw[40960];
    __nv_bfloat16* AH = (__nv_bfloat16*)(sm_raw);
    __nv_bfloat16* AL = (__nv_bfloat16*)(sm_raw + 10240);
    __nv_bfloat16* BH = (__nv_bfloat16*)(sm_raw + 20480);
    __nv_bfloat16* BL = (__nv_bfloat16*)(sm_raw + 30720);
    float* Ct = (float*)sm_raw;
    u32 sb = smem_u32(sm_raw);
    int tid = threadIdx.x, wid = tid >> 5, lane = tid & 31;
    int warpM = wid & 3, warpN = wid >> 2;
    int j0 = blockIdx.x * 128, n0 = blockIdx.y * 128, b = blockIdx.z;
    int r = tid >> 1, hf = tid & 1;
    float C[2][8][4] = {};

    for (int ch = 0; ch < 8; ch++) {
        int d0 = ch * 32;
        __syncthreads();
        {
            int j = j0 + r;
            u32 hw[8] = {}, lw[8] = {};
            if (j < NWN) {
                const float* src = aux + ((size_t)b * NS + 31 + j) * 256 + d0 + hf * 16;
#pragma unroll
                for (int i = 0; i < 4; i++)
                    split2(*(const float4*)(src + i * 4), hw + 2 * i, lw + 2 * i);
            }
            int ho = r * STR + hf * 16;
            *(uint4*)(AH + ho) = make_uint4(hw[0], hw[1], hw[2], hw[3]);
            *(uint4*)(AH + ho + 8) = make_uint4(hw[4], hw[5], hw[6], hw[7]);
            *(uint4*)(AL + ho) = make_uint4(lw[0], lw[1], lw[2], lw[3]);
            *(uint4*)(AL + ho + 8) = make_uint4(lw[4], lw[5], lw[6], lw[7]);
            const uint4* gh = (const uint4*)(g_Wkahi + (size_t)(n0 + r) * 256 + d0 + hf * 16);
            const uint4* gl = (const uint4*)(g_Wkalo + (size_t)(n0 + r) * 256 + d0 + hf * 16);
            *(uint4*)(BH + ho) = gh[0]; *(uint4*)(BH + ho + 8) = gh[1];
            *(uint4*)(BL + ho) = gl[0]; *(uint4*)(BL + ho + 8) = gl[1];
        }
        __syncthreads();
#pragma unroll
        for (int ks = 0; ks < 2; ks++) {
            u32 ah[2][4], al[2][4];
#pragma unroll
            for (int i = 0; i < 2; i++) {
                u32 off = (u32)(((warpM * 32 + i * 16 + (lane & 15)) * STR + ks * 16 + (lane >> 4) * 8) * 2);
                ldmx4(ah[i][0], ah[i][1], ah[i][2], ah[i][3], sb + off);
                ldmx4(al[i][0], al[i][1], al[i][2], al[i][3], sb + 10240 + off);
            }
            u32 bh[8][2], bl[8][2];
#pragma unroll
            for (int j = 0; j < 8; j++) {
                u32 off = (u32)(((warpN * 64 + j * 8 + (lane & 7)) * STR + ks * 16 + ((lane >> 3) & 1) * 8) * 2);
                ldmx2(bh[j][0], bh[j][1], sb + 20480 + off);
                ldmx2(bl[j][0], bl[j][1], sb + 30720 + off);
            }
#pragma unroll
            for (int i = 0; i < 2; i++)
#pragma unroll
                for (int j = 0; j < 8; j++) {
                    mma16816(C[i][j], ah[i], bh[j]);
                    mma16816(C[i][j], ah[i], bl[j]);
                    mma16816(C[i][j], al[i], bh[j]);
                }
        }
    }

#pragma unroll
    for (int half = 0; half < 2; half++) {
        __syncthreads();
        if ((warpM >> 1) == half) {
            int wm = warpM & 1;
#pragma unroll
            for (int i = 0; i < 2; i++)
#pragma unroll
                for (int j = 0; j < 8; j++) {
                    int row0 = wm * 32 + i * 16 + (lane >> 2);
                    int col = warpN * 64 + j * 8 + (lane & 3) * 2;
                    float b0 = bka[n0 + col], b1 = bka[n0 + col + 1];
                    *(float2*)&Ct[row0 * 136 + col] = make_float2(C[i][j][0] + b0, C[i][j][1] + b1);
                    *(float2*)&Ct[(row0 + 8) * 136 + col] = make_float2(C[i][j][2] + b0, C[i][j][3] + b1);
                }
        }
        __syncthreads();
        {   // per (row, 32-col head group): norm + dot with qa
            int row = tid >> 2, g = tid & 3;
            int jrow = j0 + half * 64 + row;
            if (jrow < NWN) {
                int head = (n0 >> 5) + g;
                const float* rp = Ct + row * 136 + g * 32;
                const float* qa = g_qa + (b * 8 + head) * 32;
                float ss = 0.f, dt = 0.f;
#pragma unroll 8
                for (int c = 0; c < 32; c++) { float v = rp[c]; ss += v * v; dt += qa[c] * v; }
                g_d2[(size_t)(b * 8 + head) * NS + jrow] = dt / fmaxf(sqrtf(ss), 1e-12f);
            }
        }
    }
}

// ---- dot3 via mma.sync : grid(48,1,8), 256 thr, 128x128 tile, K=128 ----
__global__ void __launch_bounds__(256) dot3_mma_kernel(const float* __restrict__ pos,
                                                       const float* __restrict__ bkp) {
    __shared__ __align__(16) char sm_raw[40960];
    __nv_bfloat16* AH = (__nv_bfloat16*)(sm_raw);
    __nv_bfloat16* AL = (__nv_bfloat16*)(sm_raw + 10240);
    __nv_bfloat16* BH = (__nv_bfloat16*)(sm_raw + 20480);
    __nv_bfloat16* BL = (__nv_bfloat16*)(sm_raw + 30720);
    float* Ct = (float*)sm_raw;
    u32 sb = smem_u32(sm_raw);
    int tid = threadIdx.x, wid = tid >> 5, lane = tid & 31;
    int warpM = wid & 3, warpN = wid >> 2;
    int j0 = blockIdx.x * 128, b = blockIdx.z;
    int r = tid >> 1, hf = tid & 1;
    float C[2][8][4] = {};

    for (int ch = 0; ch < 4; ch++) {
        int d0 = ch * 32;
        __syncthreads();
        {
            int j = j0 + r;
            u32 hw[8] = {}, lw[8] = {};
            if (j < NWN) {
                const float* src = pos + ((size_t)b * NS + 31 + j) * 128 + d0 + hf * 16;
#pragma unroll
                for (int i = 0; i < 4; i++)
                    split2(*(const float4*)(src + i * 4), hw + 2 * i, lw + 2 * i);
            }
            int ho = r * STR + hf * 16;
            *(uint4*)(AH + ho) = make_uint4(hw[0], hw[1], hw[2], hw[3]);
            *(uint4*)(AH + ho + 8) = make_uint4(hw[4], hw[5], hw[6], hw[7]);
            *(uint4*)(AL + ho) = make_uint4(lw[0], lw[1], lw[2], lw[3]);
            *(uint4*)(AL + ho + 8) = make_uint4(lw[4], lw[5], lw[6], lw[7]);
            const uint4* gh = (const uint4*)(g_Wkphi + (size_t)r * 128 + d0 + hf * 16);
            const uint4* gl = (const uint4*)(g_Wkplo + (size_t)r * 128 + d0 + hf * 16);
            *(uint4*)(BH + ho) = gh[0]; *(uint4*)(BH + ho + 8) = gh[1];
            *(uint4*)(BL + ho) = gl[0]; *(uint4*)(BL + ho + 8) = gl[1];
        }
        __syncthreads();
#pragma unroll
        for (int ks = 0; ks < 2; ks++) {
            u32 ah[2][4], al[2][4];
#pragma unroll
            for (int i = 0; i < 2; i++) {
                u32 off = (u32)(((warpM * 32 + i * 16 + (lane & 15)) * STR + ks * 16 + (lane >> 4) * 8) * 2);
                ldmx4(ah[i][0], ah[i][1], ah[i][2], ah[i][3], sb + off);
                ldmx4(al[i][0], al[i][1], al[i][2], al[i][3], sb + 10240 + off);
            }
            u32 bh[8][2], bl[8][2];
#pragma unroll
            for (int j = 0; j < 8; j++) {
                u32 off = (u32)(((warpN * 64 + j * 8 + (lane & 7)) * STR + ks * 16 + ((lane >> 3) & 1) * 8) * 2);
                ldmx2(bh[j][0], bh[j][1], sb + 20480 + off);
                ldmx2(bl[j][0], bl[j][1], sb + 30720 + off);
            }
#pragma unroll
            for (int i = 0; i < 2; i++)
#pragma unroll
                for (int j = 0; j < 8; j++) {
                    mma16816(C[i][j], ah[i], bh[j]);
                    mma16816(C[i][j], ah[i], bl[j]);
                    mma16816(C[i][j], al[i], bh[j]);
                }
        }
    }

#pragma unroll
    for (int half = 0; half < 2; half++) {
        __syncthreads();
        if ((warpM >> 1) == half) {
            int wm = warpM & 1;
#pragma unroll
            for (int i = 0; i < 2; i++)
#pragma unroll
                for (int j = 0; j < 8; j++) {
                    int row0 = wm * 32 + i * 16 + (lane >> 2);
                    int col = warpN * 64 + j * 8 + (lane & 3) * 2;
                    float b0 = bkp[col], b1 = bkp[col + 1];
                    *(float2*)&Ct[row0 * 136 + col] = make_float2(C[i][j][0] + b0, C[i][j][1] + b1);
                    *(float2*)&Ct[(row0 + 8) * 136 + col] = make_float2(C[i][j][2] + b0, C[i][j][3] + b1);
                }
        }
        __syncthreads();
#pragma unroll
        for (int q = 0; q < 2; q++) {   // per (row, 16-col head group)
            int idx = tid + q * 256;
            int row = idx >> 3, g = idx & 7;
            int jrow = j0 + half * 64 + row;
            if (jrow < NWN) {
                const float* rp = Ct + row * 136 + g * 16;
                const float* qp = g_qp + (b * 8 + g) * 16;
                float ss = 0.f, dt = 0.f;
#pragma unroll
                for (int c = 0; c < 16; c++) { float v = rp[c]; ss += v * v; dt += qp[c] * v; }
                g_d3[(size_t)(b * 8 + g) * NS + jrow] = dt / fmaxf(sqrtf(ss), 1e-12f);
            }
        }
    }
}

// ---- Q projection (last 32 rows) : grid(8h,8b), 256 thr ----
__global__ void __launch_bounds__(256) qproj_kernel(const float* __restrict__ mem,
                                                    const float* __restrict__ xpre,
                                                    const float* __restrict__ bq) {
    int h = blockIdx.x, b = blockIdx.y, tid = threadIdx.x;
    int m = tid >> 3, cg = (tid & 7) * 8;
    float acc[8] = {};
    int s = 6112 + m;
    const float* xr = (s < NSM1) ? (mem + ((size_t)b * NSM1 + s) * 512) : (xpre + b * 512);
    const float* wb = g_WqM + (h * 64 + cg) * 512;
    for (int d = 0; d < 512; d += 4) {
        float4 xv = *(const float4*)(xr + d);
#pragma unroll
        for (int c = 0; c < 8; c++) {
            float4 wv = *(const float4*)(wb + c * 512 + d);
            acc[c] += xv.x * wv.x + xv.y * wv.y + xv.z * wv.z + xv.w * wv.w;
        }
    }
    __shared__ float qs[32 * 65];
#pragma unroll
    for (int c = 0; c < 8; c++) qs[m * 65 + cg + c] = acc[c] + bq[h * 64 + cg + c];
    __syncthreads();
    if (tid < 32) {
        float ss = 0.f;
        for (int c = 0; c < 64; c++) { float v = qs[tid * 65 + c]; ss += v * v; }
        float inv = 1.f / fmaxf(sqrtf(ss), 1e-12f);
        float* dst = g_Qhat + ((b * 8 + h) * 32 + tid) * 64;
        for (int c = 0; c < 64; c++) dst[c] = qs[tid * 65 + c] * inv;
    }
}

// ---- tn: banded correlation : grid(48,8,8), 128 thr ----
__global__ void __launch_bounds__(128) tn_kernel() {
    int j0 = blockIdx.x * 128, h = blockIdx.y, b = blockIdx.z;
    int bh = b * 8 + h, tid = threadIdx.x;
    __shared__ __align__(16) float qs[32 * 64];
    __shared__ __align__(16) float Ks[159 * 36];
    for (int u = tid; u < 512; u += 128)
        ((float4*)qs)[u] = ((const float4*)(g_Qhat + bh * 2048))[u];
    float acc = 0.f;
    const float* kb = g_Khat + (size_t)bh * NS * 64;
    for (int p = 0; p < 2; p++) {
        __syncthreads();
        for (int v = tid; v < 159 * 8; v += 128) {
            int u = v >> 3, c4 = (v & 7) * 4;
            int s = j0 + u;
            float4 val = make_float4(0.f, 0.f, 0.f, 0.f);
            if (s < NS) val = *(const float4*)(kb + (size_t)s * 64 + p * 32 + c4);
            *(float4*)&Ks[u * 36 + c4] = val;
        }
        __syncthreads();
#pragma unroll 4
        for (int m = 0; m < 32; m++) {
            const float* qrow = qs + m * 64 + p * 32;
            const float* krow = Ks + (tid + m) * 36;
#pragma unroll
            for (int c = 0; c < 8; c++) {
                float4 kv = *(const float4*)(krow + c * 4);
                float4 qv = *(const float4*)(qrow + c * 4);
                acc += qv.x * kv.x + qv.y * kv.y + qv.z * kv.z + qv.w * kv.w;
            }
        }
    }
    int j = j0 + tid;
    if (j < NWN) g_tn[(size_t)bh * NS + j] = acc * (1.0f / 32.0f);
}

// ---- qa_last, qp_last ----
__global__ void qa_kernel(const float* __restrict__ aux, const float* __restrict__ Wqa,
                          const float* __restrict__ bqa) {
    int b = blockIdx.x, tid = threadIdx.x;
    int h = tid >> 5, c = tid & 31;
    const float* row = aux + ((size_t)b * NS + NS - 1) * 256;
    const float* wr = Wqa + (h * 32 + c) * 256;
    float acc = bqa[h * 32 + c];
    for (int a = 0; a < 256; a += 4) {
        float4 xv = *(const float4*)(row + a);
        float4 wv = *(const float4*)(wr + a);
        acc += xv.x * wv.x + xv.y * wv.y + xv.z * wv.z + xv.w * wv.w;
    }
    float ss = acc * acc;
#pragma unroll
    for (int o = 16; o; o >>= 1) ss += __shfl_xor_sync(0xffffffffu, ss, o);
    g_qa[(b * 8 + h) * 32 + c] = acc / fmaxf(sqrtf(ss), 1e-12f);
}

__global__ void qp_kernel(const float* __restrict__ pos, const float* __restrict__ Wqp,
                          const float* __restrict__ bqp) {
    int b = blockIdx.x, tid = threadIdx.x;
    int h = tid >> 4, c = tid & 15;
    const float* row = pos + ((size_t)b * NS + NS - 1) * 128;
    const float* wr = Wqp + (h * 16 + c) * 128;
    float acc = bqp[h * 16 + c];
    for (int a = 0; a < 128; a += 4) {
        float4 xv = *(const float4*)(row + a);
        float4 wv = *(const float4*)(wr + a);
        acc += xv.x * wv.x + xv.y * wv.y + xv.z * wv.z + xv.w * wv.w;
    }
    float ss = acc * acc;
#pragma unroll
    for (int o = 8; o; o >>= 1) ss += __shfl_xor_sync(0xffffffffu, ss, o);
    g_qp[(b * 8 + h) * 16 + c] = acc / fmaxf(sqrtf(ss), 1e-12f);
}

// ---- softmax over Wn : grid(64), 256 thr ----
__global__ void __launch_bounds__(256) softmax_kernel(const float* __restrict__ w,
                                                      const float* __restrict__ wa,
                                                      const float* __restrict__ wp) {
    int bh = blockIdx.x, tid = threadIdx.x;
    float w0 = w[0], w1 = wa[0], w2 = wp[0];
    size_t base = (size_t)bh * NS;
    __shared__ float red[256];
    float mx = -1e30f;
    for (int j = tid; j < NWN; j += 256) {
        float z = w0 * g_tn[base + j] + w1 * g_d2[base + j] + w2 * g_d3[base + j];
        g_attn[base + j] = z;
        mx = fmaxf(mx, z);
    }
    red[tid] = mx; __syncthreads();
    for (int o = 128; o; o >>= 1) { if (tid < o) red[tid] = fmaxf(red[tid], red[tid + o]); __syncthreads(); }
    mx = red[0]; __syncthreads();
    float sum = 0.f;
    for (int j = tid; j < NWN; j += 256) {
        float e = __expf(g_attn[base + j] - mx);
        g_attn[base + j] = e;
        sum += e;
    }
    red[tid] = sum; __syncthreads();
    for (int o = 128; o; o >>= 1) { if (tid < o) red[tid] += red[tid + o]; __syncthreads(); }
    float inv = 1.f / red[0];
    __syncthreads();
    for (int j = tid; j < NWN; j += 256) g_attn[base + j] *= inv;
    __syncthreads();
    if (tid == 0) g_alast[bh] = g_attn[base + NWN - 1];
}

// ---- ctx partial: grid(24,8), 512 thr ----
__global__ void __launch_bounds__(512) ctxp_kernel(const float* __restrict__ mem) {
    int wc = blockIdx.x, b = blockIdx.y, tid = threadIdx.x;
    __shared__ float at[8 * WWIN];
    int w0 = wc * WWIN;
    for (int u = tid; u < 8 * WWIN; u += 512) {
        int h = u >> 8, ww = u & (WWIN - 1);
        int w = w0 + ww;
        at[u] = (w < NWN - 1) ? g_attn[(size_t)(b * 8 + h) * NS + w] : 0.f;
    }
    __syncthreads();
    float acc[8] = {};
    const float* mb = mem + ((size_t)b * NSM1 + 31 + w0) * 512 + tid;
    if (wc < NWC - 1) {
#pragma unroll 8
        for (int ww = 0; ww < WWIN; ww++) {
            float x = mb[(size_t)ww * 512];
#pragma unroll
            for (int h2 = 0; h2 < 8; h2++) acc[h2] += at[h2 * WWIN + ww] * x;
        }
    } else {
#pragma unroll 8
        for (int ww = 0; ww < 224; ww++) {
            float x = mb[(size_t)ww * 512];
#pragma unroll
            for (int h2 = 0; h2 < 8; h2++) acc[h2] += at[h2 * WWIN + ww] * x;
        }
    }
#pragma unroll
    for (int h2 = 0; h2 < 8; h2++)
        g_ctxp[(((b * NWC + wc) * 8 + h2) << 9) + tid] = acc[h2];
}

// ---- hist : grid(8b,8h), 256 thr ----
__global__ void __launch_bounds__(256) hist_kernel(const float* __restrict__ bv) {
    int b = blockIdx.x, h = blockIdx.y, tid = threadIdx.x;
    __shared__ float ctxs[512];
    __shared__ float red[256];
    for (int d = tid; d < 512; d += 256) {
        float s = 0.f;
#pragma unroll
        for (int wc = 0; wc < NWC; wc++)
            s += g_ctxp[(((b * NWC + wc) * 8 + h) << 9) + d];
        ctxs[d] = s;
    }
    __syncthreads();
    int kk = tid >> 2, q = (tid & 3) * 128;
    const float* wr = g_WvM + (h * 64 + kk) * 512 + q;
    float acc = 0.f;
    for (int d = 0; d < 128; d += 4) {
        float4 wv = *(const float4*)(wr + d);
        acc += wv.x * ctxs[q + d] + wv.y * ctxs[q + d + 1] + wv.z * ctxs[q + d + 2] + wv.w * ctxs[q + d + 3];
    }
    red[tid] = acc;
    __syncthreads();
    if (tid < 64) {
        float a1 = 1.0f - g_alast[b * 8 + h];
        float s = red[tid * 4] + red[tid * 4 + 1] + red[tid * 4 + 2] + red[tid * 4 + 3];
        g_hist[(b * 8 + h) * 64 + tid] = s + bv[h * 64 + tid] * a1;
    }
}

// ---- GRU gi precompute : grid(31,8), 192 thr ----
__global__ void gi_kernel(const float* __restrict__ mem, const float* __restrict__ W_ih,
                          const float* __restrict__ b_ih) {
    int t = blockIdx.x, b = blockIdx.y, j = threadIdx.x;
    const float* xr = mem + ((size_t)b * NSM1 + 6112 + t) * 512;
    const float* wr = W_ih + j * 512;
    float acc = b_ih[j];
    for (int d = 0; d < 512; d += 4) {
        float4 xv = *(const float4*)(xr + d);
        float4 wv = *(const float4*)(wr + d);
        acc += xv.x * wv.x + xv.y * wv.y + xv.z * wv.z + xv.w * wv.w;
    }
    g_GI[(t * 8 + b) * 192 + j] = acc;
}

// ---- GRU scan : 1 block, 512 thr ----
__global__ void __launch_bounds__(512) scan_kernel(const float* __restrict__ W_hh,
                                                   const float* __restrict__ b_hh) {
    int tid = threadIdx.x;
    int b = tid >> 6, kk = tid & 63;
    __shared__ float hs[8 * 64];
    hs[tid] = 0.f;
    __syncthreads();
    float bhr = b_hh[kk], bhz = b_hh[64 + kk], bhn = b_hh[128 + kk];
    const float* wr = W_hh + kk * 64;
    const float* wz = W_hh + (64 + kk) * 64;
    const float* wn = W_hh + (128 + kk) * 64;
    for (int t = 0; t < 31; t++) {
        float hr = bhr, hz = bhz, hn = bhn;
        const float* hb = hs + b * 64;
#pragma unroll 8
        for (int e = 0; e < 64; e++) {
            float he = hb[e];
            hr += wr[e] * he; hz += wz[e] * he; hn += wn[e] * he;
        }
        const float* gi = g_GI + (t * 8 + b) * 192;
        float r = 1.f / (1.f + __expf(-(gi[kk] + hr)));
        float z = 1.f / (1.f + __expf(-(gi[64 + kk] + hz)));
        float nst = tanhf(gi[128 + kk] + r * hn);
        float hold = hb[kk];
        float hnew = (1.f - z) * nst + z * hold;
        __syncthreads();
        hs[tid] = hnew;
        __syncthreads();
    }
    g_res[tid] = hs[tid];
}

// ---- final output : grid(8), 512 thr ----
__global__ void __launch_bounds__(512) final_kernel(const float* __restrict__ xpre,
                                                    const float* __restrict__ bO,
                                                    float* __restrict__ out) {
    int b = blockIdx.x, tid = threadIdx.x;
    __shared__ float det[512];
    {
        int h = tid >> 6, kk = tid & 63;
        det[tid] = g_hist[(b * 8 + h) * 64 + kk] + g_alast[b * 8 + h] * g_res[b * 64 + kk];
    }
    __syncthreads();
    float acc = 0.f;
#pragma unroll 8
    for (int e = 0; e < 512; e++) acc += det[e] * g_WOMt[e * 512 + tid];
    out[b * 512 + tid] = xpre[b * 512 + tid] + acc + bO[tid];
}

extern "C" void kernel_launch(void* const* d_in, const int* in_sizes, int n_in,
                              void* d_out, int out_size) {
    const float* mem  = (const float*)d_in[0];
    const float* xpre = (const float*)d_in[1];
    const float* aux  = (const float*)d_in[2];
    const float* pos  = (const float*)d_in[3];
    const float* Wq   = (const float*)d_in[4];
    const float* bq   = (const float*)d_in[5];
    const float* Wk   = (const float*)d_in[6];
    const float* bk   = (const float*)d_in[7];
    const float* Wv   = (const float*)d_in[8];
    const float* bv   = (const float*)d_in[9];
    const float* Wqa  = (const float*)d_in[10];
    const float* bqa  = (const float*)d_in[11];
    const float* Wka  = (const float*)d_in[12];
    const float* bka  = (const float*)d_in[13];
    const float* Wqp  = (const float*)d_in[14];
    const float* bqp  = (const float*)d_in[15];
    const float* Wkp  = (const float*)d_in[16];
    const float* bkp  = (const float*)d_in[17];
    const float* W_ih = (const float*)d_in[18];
    const float* W_hh = (const float*)d_in[19];
    const float* b_ih = (const float*)d_in[20];
    const float* b_hh = (const float*)d_in[21];
    const float* WO   = (const float*)d_in[22];
    const float* bO   = (const float*)d_in[23];
    const float* w    = (const float*)d_in[24];
    const float* wa   = (const float*)d_in[25];
    const float* wp   = (const float*)d_in[26];
    const int*   G    = (const int*)d_in[27];
    float* out = (float*)d_out;

    // 4th launch = dot2_mma_kernel (ncu capture target)
    prep_kernel<<<(512 * 512 + 255) / 256, 256>>>(Wk, Wq, Wv, WO, Wka, Wkp, G);
    qa_kernel<<<8, 256>>>(aux, Wqa, bqa);
    qp_kernel<<<8, 128>>>(pos, Wqp, bqp);
    dot2_mma_kernel<<<dim3(48, 2, 8), 256>>>(aux, bka);
    kproj_mma_kernel<<<dim3(48, 4, 8), 256>>>(mem, xpre, bk);
    qproj_kernel<<<dim3(8, 8), 256>>>(mem, xpre, bq);
    dot3_mma_kernel<<<dim3(48, 1, 8), 256>>>(pos, bkp);
    tn_kernel<<<dim3(48, 8, 8), 128>>>();
    softmax_kernel<<<64, 256>>>(w, wa, wp);
    ctxp_kernel<<<dim3(NWC, 8), 512>>>(mem);
    hist_kernel<<<dim3(8, 8), 256>>>(bv);
    gi_kernel<<<dim3(31, 8), 192>>>(mem, W_ih, b_ih);
    scan_kernel<<<1, 512>>>(W_hh, b_hh);
    final_kernel<<<8, 512>>>(xpre, bO, out);
}

// round 15
// speedup vs baseline: 1.2593x; 1.0956x over previous
#include <cuda_runtime.h>
#include <cuda_bf16.h>
#include <math.h>

#define NB 8
#define NH 8
#define NS 6144
#define NSM1 6143
#define NDM 512
#define NDK 64
#define NWN 6113
#define NM 32
#define NWC 24
#define WWIN 256

typedef unsigned int u32;
typedef unsigned long long u64;

__device__ float g_WqM[512 * 512];
__device__ float g_WvM[512 * 512];
__device__ float g_WOMt[512 * 512];
__device__ __nv_bfloat16 g_Wkhi[512 * 512];
__device__ __nv_bfloat16 g_Wklo[512 * 512];
__device__ __nv_bfloat16 g_Wkahi[256 * 256];
__device__ __nv_bfloat16 g_Wkalo[256 * 256];
__device__ __nv_bfloat16 g_Wkphi[128 * 128];
__device__ __nv_bfloat16 g_Wkplo[128 * 128];
__device__ float g_Khat[(size_t)NB * NH * NS * NDK];
__device__ float g_Qhat[NB * NH * NM * NDK];
__device__ float g_qa[NB * NH * 32];
__device__ float g_qp[NB * NH * 16];
__device__ float g_tn[(size_t)NB * NH * NS];
__device__ float g_d2[(size_t)NB * NH * NS];
__device__ float g_d3[(size_t)NB * NH * NS];
__device__ float g_attn[(size_t)NB * NH * NS];
__device__ float g_alast[NB * NH];
__device__ float g_ctxp[NB * NWC * NH * NDM];
__device__ float g_hist[NB * NH * NDK];
__device__ float g_GI[31 * NB * 192];
__device__ float g_res[NB * NDK];

__device__ __forceinline__ u32 smem_u32(const void* p) {
    u32 a;
    asm("{ .reg .u64 t; cvta.to.shared.u64 t, %1; cvt.u32.u64 %0, t; }" : "=r"(a) : "l"(p));
    return a;
}
__device__ __forceinline__ void ldmx4(u32& r0, u32& r1, u32& r2, u32& r3, u32 a) {
    asm volatile("ldmatrix.sync.aligned.m8n8.x4.shared.b16 {%0,%1,%2,%3}, [%4];"
                 : "=r"(r0), "=r"(r1), "=r"(r2), "=r"(r3) : "r"(a));
}
__device__ __forceinline__ void ldmx2(u32& r0, u32& r1, u32 a) {
    asm volatile("ldmatrix.sync.aligned.m8n8.x2.shared.b16 {%0,%1}, [%2];"
                 : "=r"(r0), "=r"(r1) : "r"(a));
}
__device__ __forceinline__ void mma16816(float* c, const u32* a, const u32* b) {
    asm volatile(
        "mma.sync.aligned.m16n8k16.row.col.f32.bf16.bf16.f32 "
        "{%0,%1,%2,%3}, {%4,%5,%6,%7}, {%8,%9}, {%0,%1,%2,%3};"
        : "+f"(c[0]), "+f"(c[1]), "+f"(c[2]), "+f"(c[3])
        : "r"(a[0]), "r"(a[1]), "r"(a[2]), "r"(a[3]), "r"(b[0]), "r"(b[1]));
}
__device__ __forceinline__ void split2(float4 v, u32* hw, u32* lw) {
    __nv_bfloat16 h0 = __float2bfloat16(v.x), h1 = __float2bfloat16(v.y);
    __nv_bfloat16 h2 = __float2bfloat16(v.z), h3 = __float2bfloat16(v.w);
    float l0 = v.x - __bfloat162float(h0), l1 = v.y - __bfloat162float(h1);
    float l2 = v.z - __bfloat162float(h2), l3 = v.w - __bfloat162float(h3);
    __nv_bfloat162 ph0(h0, h1), ph1(h2, h3);
    __nv_bfloat162 pl0(__float2bfloat16(l0), __float2bfloat16(l1));
    __nv_bfloat162 pl1(__float2bfloat16(l2), __float2bfloat16(l3));
    hw[0] = *(u32*)&ph0; hw[1] = *(u32*)&ph1;
    lw[0] = *(u32*)&pl0; lw[1] = *(u32*)&pl1;
}

// ---- masked weights + hi/lo splits ----
__global__ void prep_kernel(const float* __restrict__ Wk, const float* __restrict__ Wq,
                            const float* __restrict__ Wv, const float* __restrict__ WO,
                            const float* __restrict__ Wka, const float* __restrict__ Wkp,
                            const int* __restrict__ G) {
    int i = blockIdx.x * blockDim.x + threadIdx.x;
    if (i < 512 * 512) {
        int row = i >> 9, d = i & 511;
        float gm = (float)G[(row & 63) * 64 + (d & 63)];
        float mk = Wk[i] * gm;
        __nv_bfloat16 h = __float2bfloat16(mk);
        g_Wkhi[i] = h;
        g_Wklo[i] = __float2bfloat16(mk - __bfloat162float(h));
        g_WqM[i] = Wq[i] * gm;
        g_WvM[i] = Wv[i] * gm;
        float gm2 = (float)G[(d & 63) * 64 + (row & 63)];
        g_WOMt[i] = WO[d * 512 + row] * gm2;
    }
    if (i < 256 * 256) {
        float v = Wka[i];
        __nv_bfloat16 h = __float2bfloat16(v);
        g_Wkahi[i] = h;
        g_Wkalo[i] = __float2bfloat16(v - __bfloat162float(h));
    }
    if (i < 128 * 128) {
        float v = Wkp[i];
        __nv_bfloat16 h = __float2bfloat16(v);
        g_Wkphi[i] = h;
        g_Wkplo[i] = __float2bfloat16(v - __bfloat162float(h));
    }
}

#define STR 40   // smem row stride in halves (80B, conflict-free for ldmatrix)

// ---- K projection via mma.sync bf16 hi/lo x3 : grid(48,4,8), 256 thr ----
__global__ void __launch_bounds__(256) kproj_mma_kernel(const float* __restrict__ mem,
                                                        const float* __restrict__ xpre,
                                                        const float* __restrict__ bk) {
    __shared__ __align__(16) char sm_raw[40960];
    __shared__ float invs[128];
    __nv_bfloat16* AH = (__nv_bfloat16*)(sm_raw);
    __nv_bfloat16* AL = (__nv_bfloat16*)(sm_raw + 10240);
    __nv_bfloat16* BH = (__nv_bfloat16*)(sm_raw + 20480);
    __nv_bfloat16* BL = (__nv_bfloat16*)(sm_raw + 30720);
    float* Ct = (float*)sm_raw;
    u32 sb = smem_u32(sm_raw);
    int tid = threadIdx.x, wid = tid >> 5, lane = tid & 31;
    int warpM = wid & 3, warpN = wid >> 2;
    int s0 = blockIdx.x * 128, n0 = blockIdx.y * 128, b = blockIdx.z;
    int r = tid >> 1, hf = tid & 1;
    float C[2][8][4] = {};

    for (int ch = 0; ch < 16; ch++) {
        int d0 = ch * 32;
        __syncthreads();
        {
            int s = s0 + r;
            const float* src = (s < NSM1) ? (mem + ((size_t)b * NSM1 + s) * 512 + d0 + hf * 16)
                                          : (xpre + b * 512 + d0 + hf * 16);
            u32 hw[8], lw[8];
#pragma unroll
            for (int i = 0; i < 4; i++)
                split2(*(const float4*)(src + i * 4), hw + 2 * i, lw + 2 * i);
            int ho = r * STR + hf * 16;
            *(uint4*)(AH + ho) = make_uint4(hw[0], hw[1], hw[2], hw[3]);
            *(uint4*)(AH + ho + 8) = make_uint4(hw[4], hw[5], hw[6], hw[7]);
            *(uint4*)(AL + ho) = make_uint4(lw[0], lw[1], lw[2], lw[3]);
            *(uint4*)(AL + ho + 8) = make_uint4(lw[4], lw[5], lw[6], lw[7]);
            const uint4* gh = (const uint4*)(g_Wkhi + (size_t)(n0 + r) * 512 + d0 + hf * 16);
            const uint4* gl = (const uint4*)(g_Wklo + (size_t)(n0 + r) * 512 + d0 + hf * 16);
            *(uint4*)(BH + ho) = gh[0]; *(uint4*)(BH + ho + 8) = gh[1];
            *(uint4*)(BL + ho) = gl[0]; *(uint4*)(BL + ho + 8) = gl[1];
        }
        __syncthreads();
#pragma unroll
        for (int ks = 0; ks < 2; ks++) {
            u32 ah[2][4], al[2][4];
#pragma unroll
            for (int i = 0; i < 2; i++) {
                u32 off = (u32)(((warpM * 32 + i * 16 + (lane & 15)) * STR + ks * 16 + (lane >> 4) * 8) * 2);
                ldmx4(ah[i][0], ah[i][1], ah[i][2], ah[i][3], sb + off);
                ldmx4(al[i][0], al[i][1], al[i][2], al[i][3], sb + 10240 + off);
            }
            u32 bh[8][2], bl[8][2];
#pragma unroll
            for (int j = 0; j < 8; j++) {
                u32 off = (u32)(((warpN * 64 + j * 8 + (lane & 7)) * STR + ks * 16 + ((lane >> 3) & 1) * 8) * 2);
                ldmx2(bh[j][0], bh[j][1], sb + 20480 + off);
                ldmx2(bl[j][0], bl[j][1], sb + 30720 + off);
            }
#pragma unroll
            for (int i = 0; i < 2; i++)
#pragma unroll
                for (int j = 0; j < 8; j++) {
                    mma16816(C[i][j], ah[i], bh[j]);
                    mma16816(C[i][j], ah[i], bl[j]);
                    mma16816(C[i][j], al[i], bh[j]);
                }
        }
    }

    int h0 = n0 >> 6;
#pragma unroll
    for (int half = 0; half < 2; half++) {
        __syncthreads();
        if ((warpM >> 1) == half) {
            int wm = warpM & 1;
#pragma unroll
            for (int i = 0; i < 2; i++)
#pragma unroll
                for (int j = 0; j < 8; j++) {
                    int row0 = wm * 32 + i * 16 + (lane >> 2);
                    int col = warpN * 64 + j * 8 + (lane & 3) * 2;
                    float b0 = bk[n0 + col], b1 = bk[n0 + col + 1];
                    *(float2*)&Ct[row0 * 136 + col] = make_float2(C[i][j][0] + b0, C[i][j][1] + b1);
                    *(float2*)&Ct[(row0 + 8) * 136 + col] = make_float2(C[i][j][2] + b0, C[i][j][3] + b1);
                }
        }
        __syncthreads();
        if (tid < 128) {
            int rowL = tid >> 1, hh = tid & 1;
            const float* rp = Ct + rowL * 136 + hh * 64;
            float ss = 0.f;
#pragma unroll 8
            for (int c = 0; c < 64; c++) { float v = rp[c]; ss += v * v; }
            invs[tid] = 1.0f / fmaxf(sqrtf(ss), 1e-12f);
        }
        __syncthreads();
        {
            int c4 = (tid & 31) * 4;
            int head = c4 >> 6, col64 = c4 & 63;
#pragma unroll
            for (int rr = tid >> 5; rr < 64; rr += 8) {
                float4 v = *(float4*)&Ct[rr * 136 + c4];
                float inv = invs[rr * 2 + head];
                int srow = s0 + half * 64 + rr;
                float* dst = g_Khat + (((size_t)(b * 8 + h0 + head)) * NS + srow) * 64 + col64;
                *(float4*)dst = make_float4(v.x * inv, v.y * inv, v.z * inv, v.w * inv);
            }
        }
    }
}

// ---- dot2 via mma.sync : grid(48,2,8), 256 thr, 128x128 tile, K=256 ----
__global__ void __launch_bounds__(256) dot2_mma_kernel(const float* __restrict__ aux,
                                                       const float* __restrict__ bka) {
    __shared__ __align__(16) char sm_raw[40960];
    __nv_bfloat16* AH = (__nv_bfloat16*)(sm_raw);
    __nv_bfloat16* AL = (__nv_bfloat16*)(sm_raw + 10240);
    __nv_bfloat16* BH = (__nv_bfloat16*)(sm_raw + 20480);
    __nv_bfloat16* BL = (__nv_bfloat16*)(sm_raw + 30720);
    float* Ct = (float*)sm_raw;
    u32 sb = smem_u32(sm_raw);
    int tid = threadIdx.x, wid = tid >> 5, lane = tid & 31;
    int warpM = wid & 3, warpN = wid >> 2;
    int j0 = blockIdx.x * 128, n0 = blockIdx.y * 128, b = blockIdx.z;
    int r = tid >> 1, hf = tid & 1;
    float C[2][8][4] = {};

    for (int ch = 0; ch < 8; ch++) {
        int d0 = ch * 32;
        __syncthreads();
        {
            int j = j0 + r;
            u32 hw[8] = {}, lw[8] = {};
            if (j < NWN) {
                const float* src = aux + ((size_t)b * NS + 31 + j) * 256 + d0 + hf * 16;
#pragma unroll
                for (int i = 0; i < 4; i++)
                    split2(*(const float4*)(src + i * 4), hw + 2 * i, lw + 2 * i);
            }
            int ho = r * STR + hf * 16;
            *(uint4*)(AH + ho) = make_uint4(hw[0], hw[1], hw[2], hw[3]);
            *(uint4*)(AH + ho + 8) = make_uint4(hw[4], hw[5], hw[6], hw[7]);
            *(uint4*)(AL + ho) = make_uint4(lw[0], lw[1], lw[2], lw[3]);
            *(uint4*)(AL + ho + 8) = make_uint4(lw[4], lw[5], lw[6], lw[7]);
            const uint4* gh = (const uint4*)(g_Wkahi + (size_t)(n0 + r) * 256 + d0 + hf * 16);
            const uint4* gl = (const uint4*)(g_Wkalo + (size_t)(n0 + r) * 256 + d0 + hf * 16);
            *(uint4*)(BH + ho) = gh[0]; *(uint4*)(BH + ho + 8) = gh[1];
            *(uint4*)(BL + ho) = gl[0]; *(uint4*)(BL + ho + 8) = gl[1];
        }
        __syncthreads();
#pragma unroll
        for (int ks = 0; ks < 2; ks++) {
            u32 ah[2][4], al[2][4];
#pragma unroll
            for (int i = 0; i < 2; i++) {
                u32 off = (u32)(((warpM * 32 + i * 16 + (lane & 15)) * STR + ks * 16 + (lane >> 4) * 8) * 2);
                ldmx4(ah[i][0], ah[i][1], ah[i][2], ah[i][3], sb + off);
                ldmx4(al[i][0], al[i][1], al[i][2], al[i][3], sb + 10240 + off);
            }
            u32 bh[8][2], bl[8][2];
#pragma unroll
            for (int j = 0; j < 8; j++) {
                u32 off = (u32)(((warpN * 64 + j * 8 + (lane & 7)) * STR + ks * 16 + ((lane >> 3) & 1) * 8) * 2);
                ldmx2(bh[j][0], bh[j][1], sb + 20480 + off);
                ldmx2(bl[j][0], bl[j][1], sb + 30720 + off);
            }
#pragma unroll
            for (int i = 0; i < 2; i++)
#pragma unroll
                for (int j = 0; j < 8; j++) {
                    mma16816(C[i][j], ah[i], bh[j]);
                    mma16816(C[i][j], ah[i], bl[j]);
                    mma16816(C[i][j], al[i], bh[j]);
                }
        }
    }

#pragma unroll
    for (int half = 0; half < 2; half++) {
        __syncthreads();
        if ((warpM >> 1) == half) {
            int wm = warpM & 1;
#pragma unroll
            for (int i = 0; i < 2; i++)
#pragma unroll
                for (int j = 0; j < 8; j++) {
                    int row0 = wm * 32 + i * 16 + (lane >> 2);
                    int col = warpN * 64 + j * 8 + (lane & 3) * 2;
                    float b0 = bka[n0 + col], b1 = bka[n0 + col + 1];
                    *(float2*)&Ct[row0 * 136 + col] = make_float2(C[i][j][0] + b0, C[i][j][1] + b1);
                    *(float2*)&Ct[(row0 + 8) * 136 + col] = make_float2(C[i][j][2] + b0, C[i][j][3] + b1);
                }
        }
        __syncthreads();
        {
            int row = tid >> 2, g = tid & 3;
            int jrow = j0 + half * 64 + row;
            if (jrow < NWN) {
                int head = (n0 >> 5) + g;
                const float* rp = Ct + row * 136 + g * 32;
                const float* qa = g_qa + (b * 8 + head) * 32;
                float ss = 0.f, dt = 0.f;
#pragma unroll 8
                for (int c = 0; c < 32; c++) { float v = rp[c]; ss += v * v; dt += qa[c] * v; }
                g_d2[(size_t)(b * 8 + head) * NS + jrow] = dt / fmaxf(sqrtf(ss), 1e-12f);
            }
        }
    }
}

// ---- dot3 via mma.sync : grid(48,1,8), 256 thr, 128x128 tile, K=128 ----
__global__ void __launch_bounds__(256) dot3_mma_kernel(const float* __restrict__ pos,
                                                       const float* __restrict__ bkp) {
    __shared__ __align__(16) char sm_raw[40960];
    __nv_bfloat16* AH = (__nv_bfloat16*)(sm_raw);
    __nv_bfloat16* AL = (__nv_bfloat16*)(sm_raw + 10240);
    __nv_bfloat16* BH = (__nv_bfloat16*)(sm_raw + 20480);
    __nv_bfloat16* BL = (__nv_bfloat16*)(sm_raw + 30720);
    float* Ct = (float*)sm_raw;
    u32 sb = smem_u32(sm_raw);
    int tid = threadIdx.x, wid = tid >> 5, lane = tid & 31;
    int warpM = wid & 3, warpN = wid >> 2;
    int j0 = blockIdx.x * 128, b = blockIdx.z;
    int r = tid >> 1, hf = tid & 1;
    float C[2][8][4] = {};

    for (int ch = 0; ch < 4; ch++) {
        int d0 = ch * 32;
        __syncthreads();
        {
            int j = j0 + r;
            u32 hw[8] = {}, lw[8] = {};
            if (j < NWN) {
                const float* src = pos + ((size_t)b * NS + 31 + j) * 128 + d0 + hf * 16;
#pragma unroll
                for (int i = 0; i < 4; i++)
                    split2(*(const float4*)(src + i * 4), hw + 2 * i, lw + 2 * i);
            }
            int ho = r * STR + hf * 16;
            *(uint4*)(AH + ho) = make_uint4(hw[0], hw[1], hw[2], hw[3]);
            *(uint4*)(AH + ho + 8) = make_uint4(hw[4], hw[5], hw[6], hw[7]);
            *(uint4*)(AL + ho) = make_uint4(lw[0], lw[1], lw[2], lw[3]);
            *(uint4*)(AL + ho + 8) = make_uint4(lw[4], lw[5], lw[6], lw[7]);
            const uint4* gh = (const uint4*)(g_Wkphi + (size_t)r * 128 + d0 + hf * 16);
            const uint4* gl = (const uint4*)(g_Wkplo + (size_t)r * 128 + d0 + hf * 16);
            *(uint4*)(BH + ho) = gh[0]; *(uint4*)(BH + ho + 8) = gh[1];
            *(uint4*)(BL + ho) = gl[0]; *(uint4*)(BL + ho + 8) = gl[1];
        }
        __syncthreads();
#pragma unroll
        for (int ks = 0; ks < 2; ks++) {
            u32 ah[2][4], al[2][4];
#pragma unroll
            for (int i = 0; i < 2; i++) {
                u32 off = (u32)(((warpM * 32 + i * 16 + (lane & 15)) * STR + ks * 16 + (lane >> 4) * 8) * 2);
                ldmx4(ah[i][0], ah[i][1], ah[i][2], ah[i][3], sb + off);
                ldmx4(al[i][0], al[i][1], al[i][2], al[i][3], sb + 10240 + off);
            }
            u32 bh[8][2], bl[8][2];
#pragma unroll
            for (int j = 0; j < 8; j++) {
                u32 off = (u32)(((warpN * 64 + j * 8 + (lane & 7)) * STR + ks * 16 + ((lane >> 3) & 1) * 8) * 2);
                ldmx2(bh[j][0], bh[j][1], sb + 20480 + off);
                ldmx2(bl[j][0], bl[j][1], sb + 30720 + off);
            }
#pragma unroll
            for (int i = 0; i < 2; i++)
#pragma unroll
                for (int j = 0; j < 8; j++) {
                    mma16816(C[i][j], ah[i], bh[j]);
                    mma16816(C[i][j], ah[i], bl[j]);
                    mma16816(C[i][j], al[i], bh[j]);
                }
        }
    }

#pragma unroll
    for (int half = 0; half < 2; half++) {
        __syncthreads();
        if ((warpM >> 1) == half) {
            int wm = warpM & 1;
#pragma unroll
            for (int i = 0; i < 2; i++)
#pragma unroll
                for (int j = 0; j < 8; j++) {
                    int row0 = wm * 32 + i * 16 + (lane >> 2);
                    int col = warpN * 64 + j * 8 + (lane & 3) * 2;
                    float b0 = bkp[col], b1 = bkp[col + 1];
                    *(float2*)&Ct[row0 * 136 + col] = make_float2(C[i][j][0] + b0, C[i][j][1] + b1);
                    *(float2*)&Ct[(row0 + 8) * 136 + col] = make_float2(C[i][j][2] + b0, C[i][j][3] + b1);
                }
        }
        __syncthreads();
#pragma unroll
        for (int q = 0; q < 2; q++) {
            int idx = tid + q * 256;
            int row = idx >> 3, g = idx & 7;
            int jrow = j0 + half * 64 + row;
            if (jrow < NWN) {
                const float* rp = Ct + row * 136 + g * 16;
                const float* qp = g_qp + (b * 8 + g) * 16;
                float ss = 0.f, dt = 0.f;
#pragma unroll
                for (int c = 0; c < 16; c++) { float v = rp[c]; ss += v * v; dt += qp[c] * v; }
                g_d3[(size_t)(b * 8 + g) * NS + jrow] = dt / fmaxf(sqrtf(ss), 1e-12f);
            }
        }
    }
}

// ---- Q projection (last 32 rows) : grid(8h,8b), 256 thr ----
__global__ void __launch_bounds__(256) qproj_kernel(const float* __restrict__ mem,
                                                    const float* __restrict__ xpre,
                                                    const float* __restrict__ bq) {
    int h = blockIdx.x, b = blockIdx.y, tid = threadIdx.x;
    int m = tid >> 3, cg = (tid & 7) * 8;
    float acc[8] = {};
    int s = 6112 + m;
    const float* xr = (s < NSM1) ? (mem + ((size_t)b * NSM1 + s) * 512) : (xpre + b * 512);
    const float* wb = g_WqM + (h * 64 + cg) * 512;
    for (int d = 0; d < 512; d += 4) {
        float4 xv = *(const float4*)(xr + d);
#pragma unroll
        for (int c = 0; c < 8; c++) {
            float4 wv = *(const float4*)(wb + c * 512 + d);
            acc[c] += xv.x * wv.x + xv.y * wv.y + xv.z * wv.z + xv.w * wv.w;
        }
    }
    __shared__ float qs[32 * 65];
#pragma unroll
    for (int c = 0; c < 8; c++) qs[m * 65 + cg + c] = acc[c] + bq[h * 64 + cg + c];
    __syncthreads();
    if (tid < 32) {
        float ss = 0.f;
        for (int c = 0; c < 64; c++) { float v = qs[tid * 65 + c]; ss += v * v; }
        float inv = 1.f / fmaxf(sqrtf(ss), 1e-12f);
        float* dst = g_Qhat + ((b * 8 + h) * 32 + tid) * 64;
        for (int c = 0; c < 64; c++) dst[c] = qs[tid * 65 + c] * inv;
    }
}

// ---- tn: banded correlation : grid(48,8,8), 128 thr, 4 accumulators ----
__global__ void __launch_bounds__(128) tn_kernel() {
    int j0 = blockIdx.x * 128, h = blockIdx.y, b = blockIdx.z;
    int bh = b * 8 + h, tid = threadIdx.x;
    __shared__ __align__(16) float qs[32 * 64];
    __shared__ __align__(16) float Ks[159 * 36];
    for (int u = tid; u < 512; u += 128)
        ((float4*)qs)[u] = ((const float4*)(g_Qhat + bh * 2048))[u];
    float a0 = 0.f, a1 = 0.f, a2 = 0.f, a3 = 0.f;
    const float* kb = g_Khat + (size_t)bh * NS * 64;
    for (int p = 0; p < 2; p++) {
        __syncthreads();
        for (int v = tid; v < 159 * 8; v += 128) {
            int u = v >> 3, c4 = (v & 7) * 4;
            int s = j0 + u;
            float4 val = make_float4(0.f, 0.f, 0.f, 0.f);
            if (s < NS) val = *(const float4*)(kb + (size_t)s * 64 + p * 32 + c4);
            *(float4*)&Ks[u * 36 + c4] = val;
        }
        __syncthreads();
#pragma unroll 4
        for (int m = 0; m < 32; m++) {
            const float* qrow = qs + m * 64 + p * 32;
            const float* krow = Ks + (tid + m) * 36;
#pragma unroll
            for (int c = 0; c < 8; c++) {
                float4 kv = *(const float4*)(krow + c * 4);
                float4 qv = *(const float4*)(qrow + c * 4);
                a0 += qv.x * kv.x; a1 += qv.y * kv.y;
                a2 += qv.z * kv.z; a3 += qv.w * kv.w;
            }
        }
    }
    float acc = (a0 + a1) + (a2 + a3);
    int j = j0 + tid;
    if (j < NWN) g_tn[(size_t)bh * NS + j] = acc * (1.0f / 32.0f);
}

// ---- qa_last, qp_last ----
__global__ void qa_kernel(const float* __restrict__ aux, const float* __restrict__ Wqa,
                          const float* __restrict__ bqa) {
    int b = blockIdx.x, tid = threadIdx.x;
    int h = tid >> 5, c = tid & 31;
    const float* row = aux + ((size_t)b * NS + NS - 1) * 256;
    const float* wr = Wqa + (h * 32 + c) * 256;
    float acc = bqa[h * 32 + c];
    for (int a = 0; a < 256; a += 4) {
        float4 xv = *(const float4*)(row + a);
        float4 wv = *(const float4*)(wr + a);
        acc += xv.x * wv.x + xv.y * wv.y + xv.z * wv.z + xv.w * wv.w;
    }
    float ss = acc * acc;
#pragma unroll
    for (int o = 16; o; o >>= 1) ss += __shfl_xor_sync(0xffffffffu, ss, o);
    g_qa[(b * 8 + h) * 32 + c] = acc / fmaxf(sqrtf(ss), 1e-12f);
}

__global__ void qp_kernel(const float* __restrict__ pos, const float* __restrict__ Wqp,
                          const float* __restrict__ bqp) {
    int b = blockIdx.x, tid = threadIdx.x;
    int h = tid >> 4, c = tid & 15;
    const float* row = pos + ((size_t)b * NS + NS - 1) * 128;
    const float* wr = Wqp + (h * 16 + c) * 128;
    float acc = bqp[h * 16 + c];
    for (int a = 0; a < 128; a += 4) {
        float4 xv = *(const float4*)(row + a);
        float4 wv = *(const float4*)(wr + a);
        acc += xv.x * wv.x + xv.y * wv.y + xv.z * wv.z + xv.w * wv.w;
    }
    float ss = acc * acc;
#pragma unroll
    for (int o = 8; o; o >>= 1) ss += __shfl_xor_sync(0xffffffffu, ss, o);
    g_qp[(b * 8 + h) * 16 + c] = acc / fmaxf(sqrtf(ss), 1e-12f);
}

// ---- softmax over Wn : grid(64), 256 thr ----
__global__ void __launch_bounds__(256) softmax_kernel(const float* __restrict__ w,
                                                      const float* __restrict__ wa,
                                                      const float* __restrict__ wp) {
    int bh = blockIdx.x, tid = threadIdx.x;
    float w0 = w[0], w1 = wa[0], w2 = wp[0];
    size_t base = (size_t)bh * NS;
    __shared__ float red[256];
    float mx = -1e30f;
    for (int j = tid; j < NWN; j += 256) {
        float z = w0 * g_tn[base + j] + w1 * g_d2[base + j] + w2 * g_d3[base + j];
        g_attn[base + j] = z;
        mx = fmaxf(mx, z);
    }
    red[tid] = mx; __syncthreads();
    for (int o = 128; o; o >>= 1) { if (tid < o) red[tid] = fmaxf(red[tid], red[tid + o]); __syncthreads(); }
    mx = red[0]; __syncthreads();
    float sum = 0.f;
    for (int j = tid; j < NWN; j += 256) {
        float e = __expf(g_attn[base + j] - mx);
        g_attn[base + j] = e;
        sum += e;
    }
    red[tid] = sum; __syncthreads();
    for (int o = 128; o; o >>= 1) { if (tid < o) red[tid] += red[tid + o]; __syncthreads(); }
    float inv = 1.f / red[0];
    __syncthreads();
    for (int j = tid; j < NWN; j += 256) g_attn[base + j] *= inv;
    __syncthreads();
    if (tid == 0) g_alast[bh] = g_attn[base + NWN - 1];
}

// ---- ctx partial: grid(24,8), 512 thr ----
__global__ void __launch_bounds__(512) ctxp_kernel(const float* __restrict__ mem) {
    int wc = blockIdx.x, b = blockIdx.y, tid = threadIdx.x;
    __shared__ float at[8 * WWIN];
    int w0 = wc * WWIN;
    for (int u = tid; u < 8 * WWIN; u += 512) {
        int h = u >> 8, ww = u & (WWIN - 1);
        int w = w0 + ww;
        at[u] = (w < NWN - 1) ? g_attn[(size_t)(b * 8 + h) * NS + w] : 0.f;
    }
    __syncthreads();
    float acc[8] = {};
    const float* mb = mem + ((size_t)b * NSM1 + 31 + w0) * 512 + tid;
    if (wc < NWC - 1) {
#pragma unroll 8
        for (int ww = 0; ww < WWIN; ww++) {
            float x = mb[(size_t)ww * 512];
#pragma unroll
            for (int h2 = 0; h2 < 8; h2++) acc[h2] += at[h2 * WWIN + ww] * x;
        }
    } else {
#pragma unroll 8
        for (int ww = 0; ww < 224; ww++) {
            float x = mb[(size_t)ww * 512];
#pragma unroll
            for (int h2 = 0; h2 < 8; h2++) acc[h2] += at[h2 * WWIN + ww] * x;
        }
    }
#pragma unroll
    for (int h2 = 0; h2 < 8; h2++)
        g_ctxp[(((b * NWC + wc) * 8 + h2) << 9) + tid] = acc[h2];
}

// ---- hist : grid(8b,8h), 256 thr ----
__global__ void __launch_bounds__(256) hist_kernel(const float* __restrict__ bv) {
    int b = blockIdx.x, h = blockIdx.y, tid = threadIdx.x;
    __shared__ float ctxs[512];
    __shared__ float red[256];
    for (int d = tid; d < 512; d += 256) {
        float s = 0.f;
#pragma unroll
        for (int wc = 0; wc < NWC; wc++)
            s += g_ctxp[(((b * NWC + wc) * 8 + h) << 9) + d];
        ctxs[d] = s;
    }
    __syncthreads();
    int kk = tid >> 2, q = (tid & 3) * 128;
    const float* wr = g_WvM + (h * 64 + kk) * 512 + q;
    float acc = 0.f;
    for (int d = 0; d < 128; d += 4) {
        float4 wv = *(const float4*)(wr + d);
        acc += wv.x * ctxs[q + d] + wv.y * ctxs[q + d + 1] + wv.z * ctxs[q + d + 2] + wv.w * ctxs[q + d + 3];
    }
    red[tid] = acc;
    __syncthreads();
    if (tid < 64) {
        float a1 = 1.0f - g_alast[b * 8 + h];
        float s = red[tid * 4] + red[tid * 4 + 1] + red[tid * 4 + 2] + red[tid * 4 + 3];
        g_hist[(b * 8 + h) * 64 + tid] = s + bv[h * 64 + tid] * a1;
    }
}

// ---- GRU gi precompute : grid(31,8), 192 thr ----
__global__ void gi_kernel(const float* __restrict__ mem, const float* __restrict__ W_ih,
                          const float* __restrict__ b_ih) {
    int t = blockIdx.x, b = blockIdx.y, j = threadIdx.x;
    const float* xr = mem + ((size_t)b * NSM1 + 6112 + t) * 512;
    const float* wr = W_ih + j * 512;
    float acc = b_ih[j];
    for (int d = 0; d < 512; d += 4) {
        float4 xv = *(const float4*)(xr + d);
        float4 wv = *(const float4*)(wr + d);
        acc += xv.x * wv.x + xv.y * wv.y + xv.z * wv.z + xv.w * wv.w;
    }
    g_GI[(t * 8 + b) * 192 + j] = acc;
}

// ---- GRU scan : 1 block, 512 thr ----
__global__ void __launch_bounds__(512) scan_kernel(const float* __restrict__ W_hh,
                                                   const float* __restrict__ b_hh) {
    int tid = threadIdx.x;
    int b = tid >> 6, kk = tid & 63;
    __shared__ float hs[8 * 64];
    hs[tid] = 0.f;
    __syncthreads();
    float bhr = b_hh[kk], bhz = b_hh[64 + kk], bhn = b_hh[128 + kk];
    const float* wr = W_hh + kk * 64;
    const float* wz = W_hh + (64 + kk) * 64;
    const float* wn = W_hh + (128 + kk) * 64;
    for (int t = 0; t < 31; t++) {
        float hr = bhr, hz = bhz, hn = bhn;
        const float* hb = hs + b * 64;
#pragma unroll 8
        for (int e = 0; e < 64; e++) {
            float he = hb[e];
            hr += wr[e] * he; hz += wz[e] * he; hn += wn[e] * he;
        }
        const float* gi = g_GI + (t * 8 + b) * 192;
        float r = 1.f / (1.f + __expf(-(gi[kk] + hr)));
        float z = 1.f / (1.f + __expf(-(gi[64 + kk] + hz)));
        float nst = tanhf(gi[128 + kk] + r * hn);
        float hold = hb[kk];
        float hnew = (1.f - z) * nst + z * hold;
        __syncthreads();
        hs[tid] = hnew;
        __syncthreads();
    }
    g_res[tid] = hs[tid];
}

// ---- final output : grid(8), 512 thr ----
__global__ void __launch_bounds__(512) final_kernel(const float* __restrict__ xpre,
                                                    const float* __restrict__ bO,
                                                    float* __restrict__ out) {
    int b = blockIdx.x, tid = threadIdx.x;
    __shared__ float det[512];
    {
        int h = tid >> 6, kk = tid & 63;
        det[tid] = g_hist[(b * 8 + h) * 64 + kk] + g_alast[b * 8 + h] * g_res[b * 64 + kk];
    }
    __syncthreads();
    float acc = 0.f;
#pragma unroll 8
    for (int e = 0; e < 512; e++) acc += det[e] * g_WOMt[e * 512 + tid];
    out[b * 512 + tid] = xpre[b * 512 + tid] + acc + bO[tid];
}

extern "C" void kernel_launch(void* const* d_in, const int* in_sizes, int n_in,
                              void* d_out, int out_size) {
    const float* mem  = (const float*)d_in[0];
    const float* xpre = (const float*)d_in[1];
    const float* aux  = (const float*)d_in[2];
    const float* pos  = (const float*)d_in[3];
    const float* Wq   = (const float*)d_in[4];
    const float* bq   = (const float*)d_in[5];
    const float* Wk   = (const float*)d_in[6];
    const float* bk   = (const float*)d_in[7];
    const float* Wv   = (const float*)d_in[8];
    const float* bv   = (const float*)d_in[9];
    const float* Wqa  = (const float*)d_in[10];
    const float* bqa  = (const float*)d_in[11];
    const float* Wka  = (const float*)d_in[12];
    const float* bka  = (const float*)d_in[13];
    const float* Wqp  = (const float*)d_in[14];
    const float* bqp  = (const float*)d_in[15];
    const float* Wkp  = (const float*)d_in[16];
    const float* bkp  = (const float*)d_in[17];
    const float* W_ih = (const float*)d_in[18];
    const float* W_hh = (const float*)d_in[19];
    const float* b_ih = (const float*)d_in[20];
    const float* b_hh = (const float*)d_in[21];
    const float* WO   = (const float*)d_in[22];
    const float* bO   = (const float*)d_in[23];
    const float* w    = (const float*)d_in[24];
    const float* wa   = (const float*)d_in[25];
    const float* wp   = (const float*)d_in[26];
    const int*   G    = (const int*)d_in[27];
    float* out = (float*)d_out;

    // Fork a second stream (capture-legal: event fork/join from the default stream).
    cudaStream_t s1;
    cudaStreamCreateWithFlags(&s1, cudaStreamNonBlocking);
    cudaEvent_t eFork, eJoin;
    cudaEventCreateWithFlags(&eFork, cudaEventDisableTiming);
    cudaEventCreateWithFlags(&eJoin, cudaEventDisableTiming);

    prep_kernel<<<(512 * 512 + 255) / 256, 256>>>(Wk, Wq, Wv, WO, Wka, Wkp, G);
    cudaEventRecord(eFork, 0);
    cudaStreamWaitEvent(s1, eFork, 0);

    // Branch s1: independent of Khat/Qhat chain
    qa_kernel<<<8, 256, 0, s1>>>(aux, Wqa, bqa);
    qp_kernel<<<8, 128, 0, s1>>>(pos, Wqp, bqp);
    dot2_mma_kernel<<<dim3(48, 2, 8), 256, 0, s1>>>(aux, bka);
    dot3_mma_kernel<<<dim3(48, 1, 8), 256, 0, s1>>>(pos, bkp);
    gi_kernel<<<dim3(31, 8), 192, 0, s1>>>(mem, W_ih, b_ih);
    scan_kernel<<<1, 512, 0, s1>>>(W_hh, b_hh);
    cudaEventRecord(eJoin, s1);

    // Branch s0 (default stream): K/Q projections + banded correlation
    kproj_mma_kernel<<<dim3(48, 4, 8), 256>>>(mem, xpre, bk);
    qproj_kernel<<<dim3(8, 8), 256>>>(mem, xpre, bq);
    tn_kernel<<<dim3(48, 8, 8), 128>>>();

    cudaStreamWaitEvent(0, eJoin, 0);
    softmax_kernel<<<64, 256>>>(w, wa, wp);
    ctxp_kernel<<<dim3(NWC, 8), 512>>>(mem);
    hist_kernel<<<dim3(8, 8), 256>>>(bv);
    final_kernel<<<8, 512>>>(xpre, bO, out);

    cudaStreamDestroy(s1);
    cudaEventDestroy(eFork);
    cudaEventDestroy(eJoin);
}